// round 13
// baseline (speedup 1.0000x reference)
#include <cuda_runtime.h>
#include <math.h>

#define NDST 25000
#define DIM 128
#define DT_DIM 100
#define DQ 228          // 128 + 100
#define DK 356          // 128 + 128 + 100
#define UW 712          // 2 heads * 356
#define EMAX 400000
#define LEAKYC 0.2f
#define EPSC 1e-5f

#define INV2PI 0.15915494309189535f
#define PI2_A  6.2831854820251465f
#define PI2_B  1.7484556000744415e-07f

#define SWZ(r, kp) ((((r) << 5)) | (((kp) ^ (((r) & 7) << 2)) & 31))

// ---------------- device scratch ----------------
__device__ float d_cq[DIM];
__device__ float d_QB[NDST * 2];
__device__ int   d_counts[NDST];
__device__ int   d_starts[NDST];
__device__ int   d_incl[NDST];
__device__ int   d_csum[64];
__device__ int   d_rank[EMAX];
__device__ int   d_order[EMAX];
__device__ int   d_src2[EMAX];
__device__ float d_dt2[EMAX];
__device__ __align__(16) float d_U[(size_t)NDST * UW];
__device__ __align__(16) float d_T[(size_t)NDST * UW];
__device__ __align__(16) float d_QN[(size_t)NDST * DIM];
__device__ __align__(16) float d_AGG[(size_t)NDST * DIM];
__device__ __align__(16) unsigned d_WqBH[128 * 64],  d_WqBL[128 * 64];
__device__ __align__(16) unsigned d_WkBH[2 * 384 * 32], d_WkBL[2 * 384 * 32];
__device__ __align__(16) unsigned d_WvBH[2 * 64 * 192], d_WvBL[2 * 64 * 192];
__device__ __align__(16) unsigned d_WoBH[128 * 128], d_WoBL[128 * 128];

// ---------------- bf16 split / mma / ldmatrix helpers ----------------
__device__ __forceinline__ void split2(float2 v, unsigned& hi, unsigned& lo) {
    unsigned h;
    asm("cvt.rn.bf16x2.f32 %0, %1, %2;" : "=r"(h) : "f"(v.y), "f"(v.x));
    float hx = __uint_as_float(h << 16);
    float hy = __uint_as_float(h & 0xffff0000u);
    float rx = v.x - hx, ry = v.y - hy;
    unsigned l;
    asm("cvt.rn.bf16x2.f32 %0, %1, %2;" : "=r"(l) : "f"(ry), "f"(rx));
    hi = h; lo = l;
}

__device__ __forceinline__ void mmabf(float* c, const unsigned* a, const unsigned* b) {
    asm volatile(
        "mma.sync.aligned.m16n8k16.row.col.f32.bf16.bf16.f32 "
        "{%0,%1,%2,%3},{%4,%5,%6,%7},{%8,%9},{%0,%1,%2,%3};"
        : "+f"(c[0]), "+f"(c[1]), "+f"(c[2]), "+f"(c[3])
        : "r"(a[0]), "r"(a[1]), "r"(a[2]), "r"(a[3]), "r"(b[0]), "r"(b[1]));
}

__device__ __forceinline__ void ldsm4(unsigned* r, unsigned addr) {
    asm volatile("ldmatrix.sync.aligned.m8n8.x4.shared.b16 {%0,%1,%2,%3}, [%4];"
        : "=r"(r[0]), "=r"(r[1]), "=r"(r[2]), "=r"(r[3]) : "r"(addr));
}

// ---------------- tiny setup kernels ----------------
__global__ void k_zero() {
    int i = blockIdx.x * blockDim.x + threadIdx.x;
    if (i < NDST) d_counts[i] = 0;
}

__global__ void k_prep(const float* __restrict__ Wq, const float* __restrict__ bq,
                       const float* __restrict__ b_t) {
    int j = threadIdx.x;
    float s = bq[j];
    for (int t = 0; t < DT_DIM; t++)
        s = fmaf(Wq[j * DQ + DIM + t], cosf(b_t[t]), s);
    d_cq[j] = s;
}

__global__ void k_wsplit(const float* __restrict__ Wq, const float* __restrict__ Wk,
                         const float* __restrict__ Wv, const float* __restrict__ Wout) {
    int role = blockIdx.y;
    int idx = blockIdx.x * 256 + threadIdx.x;
    unsigned hi, lo;
    if (role == 0) {
        if (idx < 128 * 64) {
            int j = idx >> 6, kp = idx & 63;
            split2(make_float2(Wq[j * DQ + 2 * kp], Wq[j * DQ + 2 * kp + 1]), hi, lo);
            d_WqBH[idx] = hi; d_WqBL[idx] = lo;
        }
    } else if (role == 1) {
        if (idx < 2 * 384 * 32) {
            int hh = idx / 12288, rem = idx % 12288;
            int c = rem >> 5, kp = rem & 31;
            float2 v = make_float2(0.f, 0.f);
            if (c < DK) {
                v.x = Wk[(size_t)(hh * 64 + 2 * kp) * DK + c];
                v.y = Wk[(size_t)(hh * 64 + 2 * kp + 1) * DK + c];
            }
            split2(v, hi, lo);
            d_WkBH[idx] = hi; d_WkBL[idx] = lo;
        }
    } else if (role == 2) {
        if (idx < 2 * 64 * 192) {
            int hh = idx / 12288, rem = idx % 12288;
            int o = rem / 192, kp = rem % 192;
            float2 v = make_float2(0.f, 0.f);
            if (kp < 178) {
                v.x = Wv[(size_t)(hh * 64 + o) * DK + 2 * kp];
                v.y = Wv[(size_t)(hh * 64 + o) * DK + 2 * kp + 1];
            }
            split2(v, hi, lo);
            d_WvBH[idx] = hi; d_WvBL[idx] = lo;
        }
    } else {
        if (idx < 128 * 128) {
            int o = idx >> 7, kp = idx & 127;
            split2(make_float2(Wout[o * 256 + 2 * kp], Wout[o * 256 + 2 * kp + 1]), hi, lo);
            d_WoBH[idx] = hi; d_WoBL[idx] = lo;
        }
    }
}

// ---------------- counting sort ----------------
__global__ void k_hist(const int* __restrict__ dst, int E) {
    int e = blockIdx.x * blockDim.x + threadIdx.x;
    if (e < E) d_rank[e] = atomicAdd(&d_counts[dst[e]], 1);
}

__global__ void k_scan1() {
    __shared__ int sm[512];
    int b = blockIdx.x, t = threadIdx.x;
    int i = b * 512 + t;
    sm[t] = (i < NDST) ? d_counts[i] : 0;
    __syncthreads();
    for (int off = 1; off < 512; off <<= 1) {
        int x = (t >= off) ? sm[t - off] : 0;
        __syncthreads();
        sm[t] += x;
        __syncthreads();
    }
    if (i < NDST) d_incl[i] = sm[t];
    if (t == 511) d_csum[b] = sm[t];
}

__global__ void k_scan3m() {
    int i = blockIdx.x * blockDim.x + threadIdx.x;
    if (i < NDST) {
        int chunk = i >> 9;
        int off = 0;
        for (int b = 0; b < chunk; b++) off += d_csum[b];
        d_starts[i] = d_incl[i] - d_counts[i] + off;
    }
}

__global__ void k_scatter(const int* __restrict__ dst, const int* __restrict__ src,
                          const float* __restrict__ dtv, int E) {
    int e = blockIdx.x * blockDim.x + threadIdx.x;
    if (e < E) {
        int pos = d_starts[dst[e]] + d_rank[e];
        d_order[pos] = e;
        d_src2[pos] = src[e];
        d_dt2[pos] = dtv[e];
    }
}

// ---------------- qn = h @ WqT + cq  -> QN, QB ----------------
__global__ void k_q(const float* __restrict__ h, const float* __restrict__ bk) {
    __shared__ __align__(16) unsigned sm[12288];
    unsigned* Ah = sm;
    unsigned* Al = sm + 2048;
    unsigned* Bh = sm + 4096;
    unsigned* Bl = sm + 8192;
    int nb = blockIdx.x * 64;
    int t = threadIdx.x;
    int w = t >> 5, lane = t & 31;
    int wm = w & 1, wn = w >> 1;
    int g = lane >> 2, tg = lane & 3;
    int arow = (lane & 7) + (((lane >> 3) & 1) << 3);
    int acsel = ((lane >> 4) << 2);
    int brow = (lane & 7) + ((lane >> 4) << 3);
    int bcsel = (((lane >> 3) & 1) << 2);
    unsigned AhB = (unsigned)__cvta_generic_to_shared(Ah);
    unsigned AlB = (unsigned)__cvta_generic_to_shared(Al);
    unsigned BhB = (unsigned)__cvta_generic_to_shared(Bh);
    unsigned BlB = (unsigned)__cvta_generic_to_shared(Bl);

    float acc[2][4][4];
#pragma unroll
    for (int mt = 0; mt < 2; mt++)
#pragma unroll
        for (int nt = 0; nt < 4; nt++)
#pragma unroll
            for (int q = 0; q < 4; q++) acc[mt][nt][q] = 0.f;

    for (int ch = 0; ch < 2; ch++) {
        for (int i = t; i < 64 * 16; i += 256) {
            int r = i >> 4, q = i & 15;
            float4 v = (nb + r < NDST)
                ? *(const float4*)&h[(size_t)(nb + r) * DIM + ch * 64 + q * 4]
                : make_float4(0.f, 0.f, 0.f, 0.f);
            unsigned h0, l0, h1, l1;
            split2(make_float2(v.x, v.y), h0, l0);
            split2(make_float2(v.z, v.w), h1, l1);
            int off = SWZ(r, q * 2);
            Ah[off] = h0; Ah[off + 1] = h1; Al[off] = l0; Al[off + 1] = l1;
        }
        for (int i = t; i < 128 * 8; i += 256) {
            int r = i >> 3, q = i & 7;
            int gidx = r * 64 + ch * 32 + q * 4;
            uint4 vh = *(const uint4*)&d_WqBH[gidx];
            uint4 vl = *(const uint4*)&d_WqBL[gidx];
            int off = SWZ(r, q * 4);
            *(uint4*)&Bh[off] = vh; *(uint4*)&Bl[off] = vl;
        }
        __syncthreads();
#pragma unroll
        for (int s = 0; s < 4; s++) {
            int kp0 = s * 8;
            unsigned ah[2][4], al2[2][4], bh[4][2], bl[4][2];
#pragma unroll
            for (int mt = 0; mt < 2; mt++) {
                int r = wm * 32 + mt * 16 + arow;
                int c = kp0 + acsel;
                ldsm4(ah[mt], AhB + 4 * SWZ(r, c));
                ldsm4(al2[mt], AlB + 4 * SWZ(r, c));
            }
#pragma unroll
            for (int p = 0; p < 2; p++) {
                int r = wn * 32 + p * 16 + brow;
                int c = kp0 + bcsel;
                unsigned t4[4];
                ldsm4(t4, BhB + 4 * SWZ(r, c));
                bh[2 * p][0] = t4[0]; bh[2 * p][1] = t4[1];
                bh[2 * p + 1][0] = t4[2]; bh[2 * p + 1][1] = t4[3];
                ldsm4(t4, BlB + 4 * SWZ(r, c));
                bl[2 * p][0] = t4[0]; bl[2 * p][1] = t4[1];
                bl[2 * p + 1][0] = t4[2]; bl[2 * p + 1][1] = t4[3];
            }
#pragma unroll
            for (int mt = 0; mt < 2; mt++)
#pragma unroll
                for (int nt = 0; nt < 4; nt++) {
                    mmabf(acc[mt][nt], ah[mt], bl[nt]);
                    mmabf(acc[mt][nt], al2[mt], bh[nt]);
                    mmabf(acc[mt][nt], ah[mt], bh[nt]);
                }
        }
        __syncthreads();
    }
    float* Rs = (float*)sm;
#pragma unroll
    for (int mt = 0; mt < 2; mt++) {
        int rl0 = wm * 32 + mt * 16 + g, rl1 = rl0 + 8;
#pragma unroll
        for (int nt = 0; nt < 4; nt++) {
            int col = wn * 32 + nt * 8 + 2 * tg;
            float c0 = d_cq[col], c1 = d_cq[col + 1];
            Rs[rl0 * 128 + col]     = acc[mt][nt][0] + c0;
            Rs[rl0 * 128 + col + 1] = acc[mt][nt][1] + c1;
            Rs[rl1 * 128 + col]     = acc[mt][nt][2] + c0;
            Rs[rl1 * 128 + col + 1] = acc[mt][nt][3] + c1;
        }
    }
    __syncthreads();
    for (int i = t; i < 64 * 32; i += 256) {
        int r = i >> 5, c4 = i & 31;
        if (nb + r < NDST)
            *(float4*)&d_QN[(size_t)(nb + r) * DIM + c4 * 4] = *(const float4*)&Rs[r * 128 + c4 * 4];
    }
    float bk0 = bk[lane], bk1 = bk[lane + 32], bk2 = bk[lane + 64], bk3 = bk[lane + 96];
    for (int rr = 0; rr < 8; rr++) {
        int row = w * 8 + rr;
        float s0 = Rs[row * 128 + lane] * bk0 + Rs[row * 128 + lane + 32] * bk1;
        float s1 = Rs[row * 128 + lane + 64] * bk2 + Rs[row * 128 + lane + 96] * bk3;
#pragma unroll
        for (int o = 16; o > 0; o >>= 1) {
            s0 += __shfl_xor_sync(0xffffffffu, s0, o);
            s1 += __shfl_xor_sync(0xffffffffu, s1, o);
        }
        if (lane == 0 && nb + row < NDST) {
            d_QB[(nb + row) * 2] = s0;
            d_QB[(nb + row) * 2 + 1] = s1;
        }
    }
}

// ---------------- U = QN_head @ Wk_head ----------------
__global__ void k_u(int dummy) {
    __shared__ __align__(16) unsigned sm[12288];
    unsigned* Ah = sm;
    unsigned* Al = sm + 2048;
    unsigned* Bh = sm + 4096;
    unsigned* Bl = sm + 8192;
    int nb = blockIdx.x * 64;
    int c0 = blockIdx.y * 128;
    int hh = blockIdx.z;
    int t = threadIdx.x;
    int w = t >> 5, lane = t & 31;
    int wm = w & 1, wn = w >> 1;
    int g = lane >> 2, tg = lane & 3;
    int arow = (lane & 7) + (((lane >> 3) & 1) << 3);
    int acsel = ((lane >> 4) << 2);
    int brow = (lane & 7) + ((lane >> 4) << 3);
    int bcsel = (((lane >> 3) & 1) << 2);
    unsigned AhB = (unsigned)__cvta_generic_to_shared(Ah);
    unsigned AlB = (unsigned)__cvta_generic_to_shared(Al);
    unsigned BhB = (unsigned)__cvta_generic_to_shared(Bh);
    unsigned BlB = (unsigned)__cvta_generic_to_shared(Bl);

    float acc[2][4][4];
#pragma unroll
    for (int mt = 0; mt < 2; mt++)
#pragma unroll
        for (int nt = 0; nt < 4; nt++)
#pragma unroll
            for (int q = 0; q < 4; q++) acc[mt][nt][q] = 0.f;

    for (int i = t; i < 64 * 16; i += 256) {
        int r = i >> 4, q = i & 15;
        float4 v = (nb + r < NDST)
            ? *(const float4*)&d_QN[(size_t)(nb + r) * DIM + hh * 64 + q * 4]
            : make_float4(0.f, 0.f, 0.f, 0.f);
        unsigned h0, l0, h1, l1;
        split2(make_float2(v.x, v.y), h0, l0);
        split2(make_float2(v.z, v.w), h1, l1);
        int off = SWZ(r, q * 2);
        Ah[off] = h0; Ah[off + 1] = h1; Al[off] = l0; Al[off + 1] = l1;
    }
    for (int i = t; i < 128 * 8; i += 256) {
        int r = i >> 3, q = i & 7;
        int gidx = (hh * 384 + c0 + r) * 32 + q * 4;
        uint4 vh = *(const uint4*)&d_WkBH[gidx];
        uint4 vl = *(const uint4*)&d_WkBL[gidx];
        int off = SWZ(r, q * 4);
        *(uint4*)&Bh[off] = vh; *(uint4*)&Bl[off] = vl;
    }
    __syncthreads();
#pragma unroll
    for (int s = 0; s < 4; s++) {
        int kp0 = s * 8;
        unsigned ah[2][4], al2[2][4], bh[4][2], bl[4][2];
#pragma unroll
        for (int mt = 0; mt < 2; mt++) {
            int r = wm * 32 + mt * 16 + arow;
            int c = kp0 + acsel;
            ldsm4(ah[mt], AhB + 4 * SWZ(r, c));
            ldsm4(al2[mt], AlB + 4 * SWZ(r, c));
        }
#pragma unroll
        for (int p = 0; p < 2; p++) {
            int r = wn * 32 + p * 16 + brow;
            int c = kp0 + bcsel;
            unsigned t4[4];
            ldsm4(t4, BhB + 4 * SWZ(r, c));
            bh[2 * p][0] = t4[0]; bh[2 * p][1] = t4[1];
            bh[2 * p + 1][0] = t4[2]; bh[2 * p + 1][1] = t4[3];
            ldsm4(t4, BlB + 4 * SWZ(r, c));
            bl[2 * p][0] = t4[0]; bl[2 * p][1] = t4[1];
            bl[2 * p + 1][0] = t4[2]; bl[2 * p + 1][1] = t4[3];
        }
#pragma unroll
        for (int mt = 0; mt < 2; mt++)
#pragma unroll
            for (int nt = 0; nt < 4; nt++) {
                mmabf(acc[mt][nt], ah[mt], bl[nt]);
                mmabf(acc[mt][nt], al2[mt], bh[nt]);
                mmabf(acc[mt][nt], ah[mt], bh[nt]);
            }
    }
#pragma unroll
    for (int mt = 0; mt < 2; mt++) {
        int r0 = nb + wm * 32 + mt * 16 + g, r1 = r0 + 8;
#pragma unroll
        for (int nt = 0; nt < 4; nt++) {
            int col = c0 + wn * 32 + nt * 8 + 2 * tg;
            if (col < DK) {
                if (r0 < NDST)
                    *(float2*)&d_U[(size_t)r0 * UW + hh * DK + col] =
                        make_float2(acc[mt][nt][0], acc[mt][nt][1]);
                if (r1 < NDST)
                    *(float2*)&d_U[(size_t)r1 * UW + hh * DK + col] =
                        make_float2(acc[mt][nt][2], acc[mt][nt][3]);
            }
        }
    }
}

// ---------------- attention: 2 warps per dst, partial softmax + smem merge ----------------
__global__ void k_attn(const float* __restrict__ h, const float* __restrict__ f,
                       const float* __restrict__ w_t, const float* __restrict__ b_t) {
    __shared__ float4 smT[4][6][32];
    __shared__ float sMS[4][4];
    int w = threadIdx.x >> 5, l = threadIdx.x & 31;
    int dl = w >> 1, half = w & 1;
    int n = blockIdx.x * 4 + dl;          // NDST % 4 == 0: always valid

    int startAll = d_starts[n];
    int cntAll = d_counts[n];
    int cnt0 = (cntAll + 1) >> 1;
    int start = startAll + (half ? cnt0 : 0);
    int cnt = half ? (cntAll - cnt0) : cnt0;

    const float4 z4 = make_float4(0.f, 0.f, 0.f, 0.f);
    const float4* up = (const float4*)(d_U + (size_t)n * UW);
    float4 Ua0 = up[l], Ua1 = up[32 + l], Ua2 = (l < 25) ? up[64 + l] : z4;
    float4 Ub0 = up[89 + l], Ub1 = up[121 + l], Ub2 = (l < 25) ? up[153 + l] : z4;
    float4 Ta0 = z4, Ta1 = z4, Ta2 = z4, Tb0 = z4, Tb1 = z4, Tb2 = z4;

    float qb0 = d_QB[n * 2], qb1 = d_QB[n * 2 + 1];
    float4 tw = (l < 25) ? ((const float4*)w_t)[l] : z4;
    float4 tb = (l < 25) ? ((const float4*)b_t)[l] : z4;

    float ninf = __int_as_float(0xff800000);
    float m0 = ninf, m1 = ninf, s0 = 0.f, s1 = 0.f;

    float4 h0v = z4, f0v = z4, h1v = z4, f1v = z4;
    if (cnt > 0) {
        h0v = ((const float4*)(h + (size_t)d_src2[start] * DIM))[l];
        f0v = __ldcs(&((const float4*)(f + (size_t)d_order[start] * DIM))[l]);
    }
    if (cnt > 1) {
        h1v = ((const float4*)(h + (size_t)d_src2[start + 1] * DIM))[l];
        f1v = __ldcs(&((const float4*)(f + (size_t)d_order[start + 1] * DIM))[l]);
    }

    for (int i = 0; i < cnt; i++) {
        float4 h2v = z4, f2v = z4;
        if (i + 2 < cnt) {
            h2v = ((const float4*)(h + (size_t)d_src2[start + i + 2] * DIM))[l];
            f2v = __ldcs(&((const float4*)(f + (size_t)d_order[start + i + 2] * DIM))[l]);
        }
        float dtc = d_dt2[start + i];

        float4 kvt = z4;
        if (l < 25) {
            float y, kk, rr;
            y = __fadd_rn(__fmul_rn(dtc, tw.x), tb.x);
            kk = rintf(y * INV2PI); rr = fmaf(-kk, PI2_A, y); rr = fmaf(kk, PI2_B, rr);
            kvt.x = __cosf(rr);
            y = __fadd_rn(__fmul_rn(dtc, tw.y), tb.y);
            kk = rintf(y * INV2PI); rr = fmaf(-kk, PI2_A, y); rr = fmaf(kk, PI2_B, rr);
            kvt.y = __cosf(rr);
            y = __fadd_rn(__fmul_rn(dtc, tw.z), tb.z);
            kk = rintf(y * INV2PI); rr = fmaf(-kk, PI2_A, y); rr = fmaf(kk, PI2_B, rr);
            kvt.z = __cosf(rr);
            y = __fadd_rn(__fmul_rn(dtc, tw.w), tb.w);
            kk = rintf(y * INV2PI); rr = fmaf(-kk, PI2_A, y); rr = fmaf(kk, PI2_B, rr);
            kvt.w = __cosf(rr);
        }

        float4 kvh = h0v, kvf = f0v;
        float sc0 = Ua0.x * kvh.x + Ua0.y * kvh.y + Ua0.z * kvh.z + Ua0.w * kvh.w;
        sc0 = fmaf(Ua1.x, kvf.x, sc0); sc0 = fmaf(Ua1.y, kvf.y, sc0);
        sc0 = fmaf(Ua1.z, kvf.z, sc0); sc0 = fmaf(Ua1.w, kvf.w, sc0);
        sc0 = fmaf(Ua2.x, kvt.x, sc0); sc0 = fmaf(Ua2.y, kvt.y, sc0);
        sc0 = fmaf(Ua2.z, kvt.z, sc0); sc0 = fmaf(Ua2.w, kvt.w, sc0);
        float sc1 = Ub0.x * kvh.x + Ub0.y * kvh.y + Ub0.z * kvh.z + Ub0.w * kvh.w;
        sc1 = fmaf(Ub1.x, kvf.x, sc1); sc1 = fmaf(Ub1.y, kvf.y, sc1);
        sc1 = fmaf(Ub1.z, kvf.z, sc1); sc1 = fmaf(Ub1.w, kvf.w, sc1);
        sc1 = fmaf(Ub2.x, kvt.x, sc1); sc1 = fmaf(Ub2.y, kvt.y, sc1);
        sc1 = fmaf(Ub2.z, kvt.z, sc1); sc1 = fmaf(Ub2.w, kvt.w, sc1);
#pragma unroll
        for (int o = 16; o > 0; o >>= 1) {
            sc0 += __shfl_xor_sync(0xffffffffu, sc0, o);
            sc1 += __shfl_xor_sync(0xffffffffu, sc1, o);
        }
        sc0 += qb0; sc1 += qb1;
        sc0 = sc0 >= 0.f ? sc0 : LEAKYC * sc0;
        sc1 = sc1 >= 0.f ? sc1 : LEAKYC * sc1;

        float nm0 = fmaxf(m0, sc0), nm1 = fmaxf(m1, sc1);
        float cr0 = __expf(m0 - nm0), cr1 = __expf(m1 - nm1);
        float e0x = __expf(sc0 - nm0), e1x = __expf(sc1 - nm1);
        s0 = s0 * cr0 + e0x;
        s1 = s1 * cr1 + e1x;
        Ta0.x = fmaf(Ta0.x, cr0, e0x * kvh.x); Ta0.y = fmaf(Ta0.y, cr0, e0x * kvh.y);
        Ta0.z = fmaf(Ta0.z, cr0, e0x * kvh.z); Ta0.w = fmaf(Ta0.w, cr0, e0x * kvh.w);
        Ta1.x = fmaf(Ta1.x, cr0, e0x * kvf.x); Ta1.y = fmaf(Ta1.y, cr0, e0x * kvf.y);
        Ta1.z = fmaf(Ta1.z, cr0, e0x * kvf.z); Ta1.w = fmaf(Ta1.w, cr0, e0x * kvf.w);
        Ta2.x = fmaf(Ta2.x, cr0, e0x * kvt.x); Ta2.y = fmaf(Ta2.y, cr0, e0x * kvt.y);
        Ta2.z = fmaf(Ta2.z, cr0, e0x * kvt.z); Ta2.w = fmaf(Ta2.w, cr0, e0x * kvt.w);
        Tb0.x = fmaf(Tb0.x, cr1, e1x * kvh.x); Tb0.y = fmaf(Tb0.y, cr1, e1x * kvh.y);
        Tb0.z = fmaf(Tb0.z, cr1, e1x * kvh.z); Tb0.w = fmaf(Tb0.w, cr1, e1x * kvh.w);
        Tb1.x = fmaf(Tb1.x, cr1, e1x * kvf.x); Tb1.y = fmaf(Tb1.y, cr1, e1x * kvf.y);
        Tb1.z = fmaf(Tb1.z, cr1, e1x * kvf.z); Tb1.w = fmaf(Tb1.w, cr1, e1x * kvf.w);
        Tb2.x = fmaf(Tb2.x, cr1, e1x * kvt.x); Tb2.y = fmaf(Tb2.y, cr1, e1x * kvt.y);
        Tb2.z = fmaf(Tb2.z, cr1, e1x * kvt.z); Tb2.w = fmaf(Tb2.w, cr1, e1x * kvt.w);
        m0 = nm0; m1 = nm1;

        h0v = h1v; f0v = f1v; h1v = h2v; f1v = f2v;
    }

    // half 1 publishes partial state
    if (half == 1) {
        smT[dl][0][l] = Ta0; smT[dl][1][l] = Ta1; smT[dl][2][l] = Ta2;
        smT[dl][3][l] = Tb0; smT[dl][4][l] = Tb1; smT[dl][5][l] = Tb2;
        if (l == 0) {
            sMS[dl][0] = m0; sMS[dl][1] = m1;
            sMS[dl][2] = s0; sMS[dl][3] = s1;
        }
    }
    __syncthreads();

    if (half == 0) {
        float mB0 = sMS[dl][0], mB1 = sMS[dl][1];
        float sB0 = sMS[dl][2], sB1 = sMS[dl][3];
        float nm0 = fmaxf(m0, mB0), nm1 = fmaxf(m1, mB1);
        float eA0 = (s0 > 0.f) ? __expf(m0 - nm0) : 0.f;
        float eB0 = (sB0 > 0.f) ? __expf(mB0 - nm0) : 0.f;
        float eA1 = (s1 > 0.f) ? __expf(m1 - nm1) : 0.f;
        float eB1 = (sB1 > 0.f) ? __expf(mB1 - nm1) : 0.f;
        float st0 = s0 * eA0 + sB0 * eB0;
        float st1 = s1 * eA1 + sB1 * eB1;
        float r0 = st0 > 0.f ? 1.f / st0 : 0.f;
        float r1 = st1 > 0.f ? 1.f / st1 : 0.f;

        float4 pb;
        float4* tp = (float4*)(d_T + (size_t)n * UW);
        pb = smT[dl][0][l];
        tp[l] = make_float4((Ta0.x * eA0 + pb.x * eB0) * r0, (Ta0.y * eA0 + pb.y * eB0) * r0,
                            (Ta0.z * eA0 + pb.z * eB0) * r0, (Ta0.w * eA0 + pb.w * eB0) * r0);
        pb = smT[dl][1][l];
        tp[32 + l] = make_float4((Ta1.x * eA0 + pb.x * eB0) * r0, (Ta1.y * eA0 + pb.y * eB0) * r0,
                                 (Ta1.z * eA0 + pb.z * eB0) * r0, (Ta1.w * eA0 + pb.w * eB0) * r0);
        if (l < 25) {
            pb = smT[dl][2][l];
            tp[64 + l] = make_float4((Ta2.x * eA0 + pb.x * eB0) * r0, (Ta2.y * eA0 + pb.y * eB0) * r0,
                                     (Ta2.z * eA0 + pb.z * eB0) * r0, (Ta2.w * eA0 + pb.w * eB0) * r0);
        }
        pb = smT[dl][3][l];
        tp[89 + l] = make_float4((Tb0.x * eA1 + pb.x * eB1) * r1, (Tb0.y * eA1 + pb.y * eB1) * r1,
                                 (Tb0.z * eA1 + pb.z * eB1) * r1, (Tb0.w * eA1 + pb.w * eB1) * r1);
        pb = smT[dl][4][l];
        tp[121 + l] = make_float4((Tb1.x * eA1 + pb.x * eB1) * r1, (Tb1.y * eA1 + pb.y * eB1) * r1,
                                  (Tb1.z * eA1 + pb.z * eB1) * r1, (Tb1.w * eA1 + pb.w * eB1) * r1);
        if (l < 25) {
            pb = smT[dl][5][l];
            tp[153 + l] = make_float4((Tb2.x * eA1 + pb.x * eB1) * r1, (Tb2.y * eA1 + pb.y * eB1) * r1,
                                      (Tb2.z * eA1 + pb.z * eB1) * r1, (Tb2.w * eA1 + pb.w * eB1) * r1);
        }
    }
}

// ---------------- agg = T_head @ Wv_head^T + bv ----------------
__global__ void k_agg(const float* __restrict__ bv) {
    __shared__ __align__(16) unsigned sm[12288];
    unsigned* Ah = sm;
    unsigned* Al = sm + 4096;
    unsigned* Bh = sm + 8192;
    unsigned* Bl = sm + 10240;
    int nb = blockIdx.x * 128;
    int hh = blockIdx.y;
    int t = threadIdx.x;
    int w = t >> 5, lane = t & 31;
    int wm = w & 3, wn = w >> 2;
    int g = lane >> 2, tg = lane & 3;
    int arow = (lane & 7) + (((lane >> 3) & 1) << 3);
    int acsel = ((lane >> 4) << 2);
    int brow = (lane & 7) + ((lane >> 4) << 3);
    int bcsel = (((lane >> 3) & 1) << 2);
    unsigned AhB = (unsigned)__cvta_generic_to_shared(Ah);
    unsigned AlB = (unsigned)__cvta_generic_to_shared(Al);
    unsigned BhB = (unsigned)__cvta_generic_to_shared(Bh);
    unsigned BlB = (unsigned)__cvta_generic_to_shared(Bl);

    float acc[2][4][4];
#pragma unroll
    for (int mt = 0; mt < 2; mt++)
#pragma unroll
        for (int nt = 0; nt < 4; nt++)
#pragma unroll
            for (int q = 0; q < 4; q++) acc[mt][nt][q] = 0.f;

    for (int ch = 0; ch < 6; ch++) {
        for (int i = t; i < 128 * 16; i += 256) {
            int r = i >> 4, q = i & 15;
            int idx4 = ch * 16 + q;
            float4 v = make_float4(0.f, 0.f, 0.f, 0.f);
            if (nb + r < NDST && idx4 < 89) {
                const float* src = d_T + (size_t)(nb + r) * UW + hh * DK + idx4 * 4;
                float2 v01 = *(const float2*)src;
                float2 v23 = *(const float2*)(src + 2);
                v = make_float4(v01.x, v01.y, v23.x, v23.y);
            }
            unsigned h0, l0, h1, l1;
            split2(make_float2(v.x, v.y), h0, l0);
            split2(make_float2(v.z, v.w), h1, l1);
            int off = SWZ(r, q * 2);
            Ah[off] = h0; Ah[off + 1] = h1; Al[off] = l0; Al[off + 1] = l1;
        }
        for (int i = t; i < 64 * 8; i += 256) {
            int r = i >> 3, q = i & 7;
            int gidx = (hh * 64 + r) * 192 + ch * 32 + q * 4;
            uint4 vh = *(const uint4*)&d_WvBH[gidx];
            uint4 vl = *(const uint4*)&d_WvBL[gidx];
            int off = SWZ(r, q * 4);
            *(uint4*)&Bh[off] = vh; *(uint4*)&Bl[off] = vl;
        }
        __syncthreads();
#pragma unroll
        for (int s = 0; s < 4; s++) {
            int kp0 = s * 8;
            unsigned ah[2][4], al2[2][4], bh[4][2], bl[4][2];
#pragma unroll
            for (int mt = 0; mt < 2; mt++) {
                int r = wm * 32 + mt * 16 + arow;
                int c = kp0 + acsel;
                ldsm4(ah[mt], AhB + 4 * SWZ(r, c));
                ldsm4(al2[mt], AlB + 4 * SWZ(r, c));
            }
#pragma unroll
            for (int p = 0; p < 2; p++) {
                int r = wn * 32 + p * 16 + brow;
                int c = kp0 + bcsel;
                unsigned t4[4];
                ldsm4(t4, BhB + 4 * SWZ(r, c));
                bh[2 * p][0] = t4[0]; bh[2 * p][1] = t4[1];
                bh[2 * p + 1][0] = t4[2]; bh[2 * p + 1][1] = t4[3];
                ldsm4(t4, BlB + 4 * SWZ(r, c));
                bl[2 * p][0] = t4[0]; bl[2 * p][1] = t4[1];
                bl[2 * p + 1][0] = t4[2]; bl[2 * p + 1][1] = t4[3];
            }
#pragma unroll
            for (int mt = 0; mt < 2; mt++)
#pragma unroll
                for (int nt = 0; nt < 4; nt++) {
                    mmabf(acc[mt][nt], ah[mt], bl[nt]);
                    mmabf(acc[mt][nt], al2[mt], bh[nt]);
                    mmabf(acc[mt][nt], ah[mt], bh[nt]);
                }
        }
        __syncthreads();
    }
#pragma unroll
    for (int mt = 0; mt < 2; mt++) {
        int r0 = nb + wm * 32 + mt * 16 + g, r1 = r0 + 8;
        int has0 = (r0 < NDST) ? d_counts[r0] : 0;
        int has1 = (r1 < NDST) ? d_counts[r1] : 0;
#pragma unroll
        for (int nt = 0; nt < 4; nt++) {
            int col = hh * 64 + wn * 32 + nt * 8 + 2 * tg;
            float b0 = bv[col], b1 = bv[col + 1];
            if (r0 < NDST)
                *(float2*)&d_AGG[(size_t)r0 * DIM + col] = make_float2(
                    acc[mt][nt][0] + (has0 > 0 ? b0 : 0.f),
                    acc[mt][nt][1] + (has0 > 0 ? b1 : 0.f));
            if (r1 < NDST)
                *(float2*)&d_AGG[(size_t)r1 * DIM + col] = make_float2(
                    acc[mt][nt][2] + (has1 > 0 ? b0 : 0.f),
                    acc[mt][nt][3] + (has1 > 0 ? b1 : 0.f));
        }
    }
}

// ---------------- rst = relu([agg,h] @ Wout^T + bout) -> LayerNorm ----------------
__global__ void k_out(const float* __restrict__ h, const float* __restrict__ bout,
                      const float* __restrict__ ln_w, const float* __restrict__ ln_b,
                      float* __restrict__ out) {
    __shared__ __align__(16) unsigned sm[12288];
    unsigned* Ah = sm;
    unsigned* Al = sm + 2048;
    unsigned* Bh = sm + 4096;
    unsigned* Bl = sm + 8192;
    float* Rs = (float*)(sm + 4096);
    int nb = blockIdx.x * 64;
    int t = threadIdx.x;
    int w = t >> 5, lane = t & 31;
    int wm = w & 1, wn = w >> 1;
    int g = lane >> 2, tg = lane & 3;
    int arow = (lane & 7) + (((lane >> 3) & 1) << 3);
    int acsel = ((lane >> 4) << 2);
    int brow = (lane & 7) + ((lane >> 4) << 3);
    int bcsel = (((lane >> 3) & 1) << 2);
    unsigned AhB = (unsigned)__cvta_generic_to_shared(Ah);
    unsigned AlB = (unsigned)__cvta_generic_to_shared(Al);
    unsigned BhB = (unsigned)__cvta_generic_to_shared(Bh);
    unsigned BlB = (unsigned)__cvta_generic_to_shared(Bl);

    float acc[2][4][4];
#pragma unroll
    for (int mt = 0; mt < 2; mt++)
#pragma unroll
        for (int nt = 0; nt < 4; nt++)
#pragma unroll
            for (int q = 0; q < 4; q++) acc[mt][nt][q] = 0.f;

    for (int ch = 0; ch < 4; ch++) {
        const float* srcp = (ch < 2) ? (d_AGG + ch * 64) : (h + (ch - 2) * 64);
        for (int i = t; i < 64 * 16; i += 256) {
            int r = i >> 4, q = i & 15;
            float4 v = (nb + r < NDST)
                ? *(const float4*)&srcp[(size_t)(nb + r) * DIM + q * 4]
                : make_float4(0.f, 0.f, 0.f, 0.f);
            unsigned h0, l0, h1, l1;
            split2(make_float2(v.x, v.y), h0, l0);
            split2(make_float2(v.z, v.w), h1, l1);
            int off = SWZ(r, q * 2);
            Ah[off] = h0; Ah[off + 1] = h1; Al[off] = l0; Al[off + 1] = l1;
        }
        for (int i = t; i < 128 * 8; i += 256) {
            int r = i >> 3, q = i & 7;
            int gidx = r * 128 + ch * 32 + q * 4;
            uint4 vh = *(const uint4*)&d_WoBH[gidx];
            uint4 vl = *(const uint4*)&d_WoBL[gidx];
            int off = SWZ(r, q * 4);
            *(uint4*)&Bh[off] = vh; *(uint4*)&Bl[off] = vl;
        }
        __syncthreads();
#pragma unroll
        for (int s = 0; s < 4; s++) {
            int kp0 = s * 8;
            unsigned ah[2][4], al2[2][4], bh[4][2], bl[4][2];
#pragma unroll
            for (int mt = 0; mt < 2; mt++) {
                int r = wm * 32 + mt * 16 + arow;
                int c = kp0 + acsel;
                ldsm4(ah[mt], AhB + 4 * SWZ(r, c));
                ldsm4(al2[mt], AlB + 4 * SWZ(r, c));
            }
#pragma unroll
            for (int p = 0; p < 2; p++) {
                int r = wn * 32 + p * 16 + brow;
                int c = kp0 + bcsel;
                unsigned t4[4];
                ldsm4(t4, BhB + 4 * SWZ(r, c));
                bh[2 * p][0] = t4[0]; bh[2 * p][1] = t4[1];
                bh[2 * p + 1][0] = t4[2]; bh[2 * p + 1][1] = t4[3];
                ldsm4(t4, BlB + 4 * SWZ(r, c));
                bl[2 * p][0] = t4[0]; bl[2 * p][1] = t4[1];
                bl[2 * p + 1][0] = t4[2]; bl[2 * p + 1][1] = t4[3];
            }
#pragma unroll
            for (int mt = 0; mt < 2; mt++)
#pragma unroll
                for (int nt = 0; nt < 4; nt++) {
                    mmabf(acc[mt][nt], ah[mt], bl[nt]);
                    mmabf(acc[mt][nt], al2[mt], bh[nt]);
                    mmabf(acc[mt][nt], ah[mt], bh[nt]);
                }
        }
        __syncthreads();
    }

#pragma unroll
    for (int mt = 0; mt < 2; mt++) {
        int rl0 = wm * 32 + mt * 16 + g, rl1 = rl0 + 8;
#pragma unroll
        for (int nt = 0; nt < 4; nt++) {
            int col = wn * 32 + nt * 8 + 2 * tg;
            float b0 = bout[col], b1 = bout[col + 1];
            Rs[rl0 * 128 + col]     = fmaxf(acc[mt][nt][0] + b0, 0.f);
            Rs[rl0 * 128 + col + 1] = fmaxf(acc[mt][nt][1] + b1, 0.f);
            Rs[rl1 * 128 + col]     = fmaxf(acc[mt][nt][2] + b0, 0.f);
            Rs[rl1 * 128 + col + 1] = fmaxf(acc[mt][nt][3] + b1, 0.f);
        }
    }
    __syncthreads();

    int l = lane;
    float lw0 = ln_w[l], lw1 = ln_w[l + 32], lw2 = ln_w[l + 64], lw3 = ln_w[l + 96];
    float lb0 = ln_b[l], lb1 = ln_b[l + 32], lb2 = ln_b[l + 64], lb3 = ln_b[l + 96];
    for (int rr = 0; rr < 8; rr++) {
        int nl = w * 8 + rr;
        float v0 = Rs[nl * 128 + l], v1 = Rs[nl * 128 + l + 32];
        float v2 = Rs[nl * 128 + l + 64], v3 = Rs[nl * 128 + l + 96];
        float s = v0 + v1 + v2 + v3;
#pragma unroll
        for (int off = 16; off > 0; off >>= 1) s += __shfl_xor_sync(0xffffffffu, s, off);
        float mu = s * (1.f / 128.f);
        float d0 = v0 - mu, d1 = v1 - mu, d2 = v2 - mu, d3 = v3 - mu;
        float vs = d0 * d0 + d1 * d1 + d2 * d2 + d3 * d3;
#pragma unroll
        for (int off = 16; off > 0; off >>= 1) vs += __shfl_xor_sync(0xffffffffu, vs, off);
        float rstd = rsqrtf(vs * (1.f / 128.f) + EPSC);
        int ng = nb + nl;
        if (ng < NDST) {
            float* op = out + (size_t)ng * DIM;
            op[l] = d0 * rstd * lw0 + lb0;
            op[l + 32] = d1 * rstd * lw1 + lb1;
            op[l + 64] = d2 * rstd * lw2 + lb2;
            op[l + 96] = d3 * rstd * lw3 + lb3;
        }
    }
}

// ---------------- launch (fork/join; R10 structure + split-warp attn) ----------------
extern "C" void kernel_launch(void* const* d_in, const int* in_sizes, int n_in,
                              void* d_out, int out_size) {
    const float* h       = (const float*)d_in[0];
    const float* f       = (const float*)d_in[1];
    const float* dt      = (const float*)d_in[2];
    const int*   src_idx = (const int*)d_in[3];
    const int*   dst_idx = (const int*)d_in[4];
    const float* w_t     = (const float*)d_in[5];
    const float* b_t     = (const float*)d_in[6];
    const float* Wq      = (const float*)d_in[7];
    const float* bq      = (const float*)d_in[8];
    const float* Wk      = (const float*)d_in[9];
    const float* bk      = (const float*)d_in[10];
    const float* Wv      = (const float*)d_in[11];
    const float* bv      = (const float*)d_in[12];
    const float* Wout    = (const float*)d_in[13];
    const float* bout    = (const float*)d_in[14];
    const float* ln_w    = (const float*)d_in[15];
    const float* ln_b    = (const float*)d_in[16];
    float* out = (float*)d_out;

    int E = in_sizes[2];
    int nch = (NDST + 511) / 512;
    int nb64 = (NDST + 63) / 64;
    int nb128 = (NDST + 127) / 128;

    static cudaStream_t s2 = nullptr;
    static cudaEvent_t evFork = nullptr, evJoin = nullptr;
    if (s2 == nullptr) {
        cudaStreamCreateWithFlags(&s2, cudaStreamNonBlocking);
        cudaEventCreateWithFlags(&evFork, cudaEventDisableTiming);
        cudaEventCreateWithFlags(&evJoin, cudaEventDisableTiming);
    }

    cudaEventRecord(evFork, 0);
    cudaStreamWaitEvent(s2, evFork, 0);

    // sort branch (s2)
    k_zero<<<(NDST + 255) / 256, 256, 0, s2>>>();
    k_hist<<<(E + 255) / 256, 256, 0, s2>>>(dst_idx, E);
    k_scan1<<<nch, 512, 0, s2>>>();
    k_scan3m<<<(NDST + 255) / 256, 256, 0, s2>>>();
    k_scatter<<<(E + 255) / 256, 256, 0, s2>>>(dst_idx, src_idx, dt, E);
    cudaEventRecord(evJoin, s2);

    // GEMM branch (default stream)
    k_prep<<<1, 128>>>(Wq, bq, b_t);
    k_wsplit<<<dim3(96, 4), 256>>>(Wq, Wk, Wv, Wout);
    k_q<<<nb64, 256>>>(h, bk);
    k_u<<<dim3(nb64, 3, 2), 256>>>(0);

    cudaStreamWaitEvent(0, evJoin, 0);
    k_attn<<<NDST / 4, 256>>>(h, f, w_t, b_t);
    k_agg<<<dim3(nb128, 2), 256>>>(bv);
    k_out<<<nb64, 256>>>(h, bout, ln_w, ln_b, out);
}

// round 14
// speedup vs baseline: 1.4122x; 1.4122x over previous
#include <cuda_runtime.h>
#include <math.h>

#define NDST 25000
#define DIM 128
#define DT_DIM 100
#define DQ 228          // 128 + 100
#define DK 356          // 128 + 128 + 100
#define UW 712          // 2 heads * 356
#define EMAX 400000
#define LEAKYC 0.2f
#define EPSC 1e-5f

#define INV2PI 0.15915494309189535f
#define PI2_A  6.2831854820251465f
#define PI2_B  1.7484556000744415e-07f

// swizzled smem index: row stride 32 u32, 16B chunks xor'd by (r&7) -> ldmatrix-compatible
#define SWZ(r, kp) ((((r) << 5)) | (((kp) ^ (((r) & 7) << 2)) & 31))

// ---------------- device scratch ----------------
__device__ float d_cq[DIM];
__device__ float d_QB[NDST * 2];
__device__ int   d_counts[NDST];
__device__ int   d_starts[NDST];
__device__ int   d_incl[NDST];
__device__ int   d_csum[64];
__device__ int   d_rank[EMAX];
__device__ int   d_order[EMAX];
__device__ int   d_src2[EMAX];
__device__ float d_dt2[EMAX];
__device__ __align__(16) float d_U[(size_t)NDST * UW];
__device__ __align__(16) float d_T[(size_t)NDST * UW];
__device__ __align__(16) float d_QN[(size_t)NDST * DIM];
__device__ __align__(16) float d_AGG[(size_t)NDST * DIM];
__device__ __align__(16) unsigned d_WqBH[128 * 64],  d_WqBL[128 * 64];
__device__ __align__(16) unsigned d_WkBH[2 * 384 * 32], d_WkBL[2 * 384 * 32];
__device__ __align__(16) unsigned d_WvBH[2 * 64 * 192], d_WvBL[2 * 64 * 192];
__device__ __align__(16) unsigned d_WoBH[128 * 128], d_WoBL[128 * 128];

// ---------------- bf16 split / mma / ldmatrix helpers ----------------
__device__ __forceinline__ void split2(float2 v, unsigned& hi, unsigned& lo) {
    unsigned h;
    asm("cvt.rn.bf16x2.f32 %0, %1, %2;" : "=r"(h) : "f"(v.y), "f"(v.x));
    float hx = __uint_as_float(h << 16);
    float hy = __uint_as_float(h & 0xffff0000u);
    float rx = v.x - hx, ry = v.y - hy;
    unsigned l;
    asm("cvt.rn.bf16x2.f32 %0, %1, %2;" : "=r"(l) : "f"(ry), "f"(rx));
    hi = h; lo = l;
}

__device__ __forceinline__ void mmabf(float* c, const unsigned* a, const unsigned* b) {
    asm volatile(
        "mma.sync.aligned.m16n8k16.row.col.f32.bf16.bf16.f32 "
        "{%0,%1,%2,%3},{%4,%5,%6,%7},{%8,%9},{%0,%1,%2,%3};"
        : "+f"(c[0]), "+f"(c[1]), "+f"(c[2]), "+f"(c[3])
        : "r"(a[0]), "r"(a[1]), "r"(a[2]), "r"(a[3]), "r"(b[0]), "r"(b[1]));
}

__device__ __forceinline__ void ldsm4(unsigned* r, unsigned addr) {
    asm volatile("ldmatrix.sync.aligned.m8n8.x4.shared.b16 {%0,%1,%2,%3}, [%4];"
        : "=r"(r[0]), "=r"(r[1]), "=r"(r[2]), "=r"(r[3]) : "r"(addr));
}

// ---------------- tiny setup kernels ----------------
__global__ void k_zero() {
    int i = blockIdx.x * blockDim.x + threadIdx.x;
    if (i < NDST) d_counts[i] = 0;
}

__global__ void k_prep(const float* __restrict__ Wq, const float* __restrict__ bq,
                       const float* __restrict__ b_t) {
    int j = threadIdx.x;
    float s = bq[j];
    for (int t = 0; t < DT_DIM; t++)
        s = fmaf(Wq[j * DQ + DIM + t], cosf(b_t[t]), s);
    d_cq[j] = s;
}

__global__ void k_wsplit(const float* __restrict__ Wq, const float* __restrict__ Wk,
                         const float* __restrict__ Wv, const float* __restrict__ Wout) {
    int role = blockIdx.y;
    int idx = blockIdx.x * 256 + threadIdx.x;
    unsigned hi, lo;
    if (role == 0) {
        if (idx < 128 * 64) {
            int j = idx >> 6, kp = idx & 63;
            split2(make_float2(Wq[j * DQ + 2 * kp], Wq[j * DQ + 2 * kp + 1]), hi, lo);
            d_WqBH[idx] = hi; d_WqBL[idx] = lo;
        }
    } else if (role == 1) {
        if (idx < 2 * 384 * 32) {
            int hh = idx / 12288, rem = idx % 12288;
            int c = rem >> 5, kp = rem & 31;
            float2 v = make_float2(0.f, 0.f);
            if (c < DK) {
                v.x = Wk[(size_t)(hh * 64 + 2 * kp) * DK + c];
                v.y = Wk[(size_t)(hh * 64 + 2 * kp + 1) * DK + c];
            }
            split2(v, hi, lo);
            d_WkBH[idx] = hi; d_WkBL[idx] = lo;
        }
    } else if (role == 2) {
        if (idx < 2 * 64 * 192) {
            int hh = idx / 12288, rem = idx % 12288;
            int o = rem / 192, kp = rem % 192;
            float2 v = make_float2(0.f, 0.f);
            if (kp < 178) {
                v.x = Wv[(size_t)(hh * 64 + o) * DK + 2 * kp];
                v.y = Wv[(size_t)(hh * 64 + o) * DK + 2 * kp + 1];
            }
            split2(v, hi, lo);
            d_WvBH[idx] = hi; d_WvBL[idx] = lo;
        }
    } else {
        if (idx < 128 * 128) {
            int o = idx >> 7, kp = idx & 127;
            split2(make_float2(Wout[o * 256 + 2 * kp], Wout[o * 256 + 2 * kp + 1]), hi, lo);
            d_WoBH[idx] = hi; d_WoBL[idx] = lo;
        }
    }
}

// ---------------- counting sort ----------------
__global__ void k_hist(const int* __restrict__ dst, int E) {
    int e = blockIdx.x * blockDim.x + threadIdx.x;
    if (e < E) d_rank[e] = atomicAdd(&d_counts[dst[e]], 1);
}

__global__ void k_scan1() {
    __shared__ int sm[512];
    int b = blockIdx.x, t = threadIdx.x;
    int i = b * 512 + t;
    sm[t] = (i < NDST) ? d_counts[i] : 0;
    __syncthreads();
    for (int off = 1; off < 512; off <<= 1) {
        int x = (t >= off) ? sm[t - off] : 0;
        __syncthreads();
        sm[t] += x;
        __syncthreads();
    }
    if (i < NDST) d_incl[i] = sm[t];
    if (t == 511) d_csum[b] = sm[t];
}

__global__ void k_scan3m() {
    int i = blockIdx.x * blockDim.x + threadIdx.x;
    if (i < NDST) {
        int chunk = i >> 9;
        int off = 0;
        for (int b = 0; b < chunk; b++) off += d_csum[b];
        d_starts[i] = d_incl[i] - d_counts[i] + off;
    }
}

__global__ void k_scatter(const int* __restrict__ dst, const int* __restrict__ src,
                          const float* __restrict__ dtv, int E) {
    int e = blockIdx.x * blockDim.x + threadIdx.x;
    if (e < E) {
        int pos = d_starts[dst[e]] + d_rank[e];
        d_order[pos] = e;
        d_src2[pos] = src[e];
        d_dt2[pos] = dtv[e];
    }
}

// ---------------- qn = h @ WqT + cq  -> QN, QB ----------------
__global__ void k_q(const float* __restrict__ h, const float* __restrict__ bk) {
    __shared__ __align__(16) unsigned sm[12288];
    unsigned* Ah = sm;
    unsigned* Al = sm + 2048;
    unsigned* Bh = sm + 4096;
    unsigned* Bl = sm + 8192;
    int nb = blockIdx.x * 64;
    int t = threadIdx.x;
    int w = t >> 5, lane = t & 31;
    int wm = w & 1, wn = w >> 1;
    int g = lane >> 2, tg = lane & 3;
    int arow = (lane & 7) + (((lane >> 3) & 1) << 3);
    int acsel = ((lane >> 4) << 2);
    int brow = (lane & 7) + ((lane >> 4) << 3);
    int bcsel = (((lane >> 3) & 1) << 2);
    unsigned AhB = (unsigned)__cvta_generic_to_shared(Ah);
    unsigned AlB = (unsigned)__cvta_generic_to_shared(Al);
    unsigned BhB = (unsigned)__cvta_generic_to_shared(Bh);
    unsigned BlB = (unsigned)__cvta_generic_to_shared(Bl);

    float acc[2][4][4];
#pragma unroll
    for (int mt = 0; mt < 2; mt++)
#pragma unroll
        for (int nt = 0; nt < 4; nt++)
#pragma unroll
            for (int q = 0; q < 4; q++) acc[mt][nt][q] = 0.f;

    for (int ch = 0; ch < 2; ch++) {
        for (int i = t; i < 64 * 16; i += 256) {
            int r = i >> 4, q = i & 15;
            float4 v = (nb + r < NDST)
                ? *(const float4*)&h[(size_t)(nb + r) * DIM + ch * 64 + q * 4]
                : make_float4(0.f, 0.f, 0.f, 0.f);
            unsigned h0, l0, h1, l1;
            split2(make_float2(v.x, v.y), h0, l0);
            split2(make_float2(v.z, v.w), h1, l1);
            int off = SWZ(r, q * 2);
            Ah[off] = h0; Ah[off + 1] = h1; Al[off] = l0; Al[off + 1] = l1;
        }
        for (int i = t; i < 128 * 8; i += 256) {
            int r = i >> 3, q = i & 7;
            int gidx = r * 64 + ch * 32 + q * 4;
            uint4 vh = *(const uint4*)&d_WqBH[gidx];
            uint4 vl = *(const uint4*)&d_WqBL[gidx];
            int off = SWZ(r, q * 4);
            *(uint4*)&Bh[off] = vh; *(uint4*)&Bl[off] = vl;
        }
        __syncthreads();
#pragma unroll
        for (int s = 0; s < 4; s++) {
            int kp0 = s * 8;
            unsigned ah[2][4], al2[2][4], bh[4][2], bl[4][2];
#pragma unroll
            for (int mt = 0; mt < 2; mt++) {
                int r = wm * 32 + mt * 16 + arow;
                int c = kp0 + acsel;
                ldsm4(ah[mt], AhB + 4 * SWZ(r, c));
                ldsm4(al2[mt], AlB + 4 * SWZ(r, c));
            }
#pragma unroll
            for (int p = 0; p < 2; p++) {
                int r = wn * 32 + p * 16 + brow;
                int c = kp0 + bcsel;
                unsigned t4[4];
                ldsm4(t4, BhB + 4 * SWZ(r, c));
                bh[2 * p][0] = t4[0]; bh[2 * p][1] = t4[1];
                bh[2 * p + 1][0] = t4[2]; bh[2 * p + 1][1] = t4[3];
                ldsm4(t4, BlB + 4 * SWZ(r, c));
                bl[2 * p][0] = t4[0]; bl[2 * p][1] = t4[1];
                bl[2 * p + 1][0] = t4[2]; bl[2 * p + 1][1] = t4[3];
            }
#pragma unroll
            for (int mt = 0; mt < 2; mt++)
#pragma unroll
                for (int nt = 0; nt < 4; nt++) {
                    mmabf(acc[mt][nt], ah[mt], bl[nt]);
                    mmabf(acc[mt][nt], al2[mt], bh[nt]);
                    mmabf(acc[mt][nt], ah[mt], bh[nt]);
                }
        }
        __syncthreads();
    }
    float* Rs = (float*)sm;
#pragma unroll
    for (int mt = 0; mt < 2; mt++) {
        int rl0 = wm * 32 + mt * 16 + g, rl1 = rl0 + 8;
#pragma unroll
        for (int nt = 0; nt < 4; nt++) {
            int col = wn * 32 + nt * 8 + 2 * tg;
            float c0 = d_cq[col], c1 = d_cq[col + 1];
            Rs[rl0 * 128 + col]     = acc[mt][nt][0] + c0;
            Rs[rl0 * 128 + col + 1] = acc[mt][nt][1] + c1;
            Rs[rl1 * 128 + col]     = acc[mt][nt][2] + c0;
            Rs[rl1 * 128 + col + 1] = acc[mt][nt][3] + c1;
        }
    }
    __syncthreads();
    for (int i = t; i < 64 * 32; i += 256) {
        int r = i >> 5, c4 = i & 31;
        if (nb + r < NDST)
            *(float4*)&d_QN[(size_t)(nb + r) * DIM + c4 * 4] = *(const float4*)&Rs[r * 128 + c4 * 4];
    }
    float bk0 = bk[lane], bk1 = bk[lane + 32], bk2 = bk[lane + 64], bk3 = bk[lane + 96];
    for (int rr = 0; rr < 8; rr++) {
        int row = w * 8 + rr;
        float s0 = Rs[row * 128 + lane] * bk0 + Rs[row * 128 + lane + 32] * bk1;
        float s1 = Rs[row * 128 + lane + 64] * bk2 + Rs[row * 128 + lane + 96] * bk3;
#pragma unroll
        for (int o = 16; o > 0; o >>= 1) {
            s0 += __shfl_xor_sync(0xffffffffu, s0, o);
            s1 += __shfl_xor_sync(0xffffffffu, s1, o);
        }
        if (lane == 0 && nb + row < NDST) {
            d_QB[(nb + row) * 2] = s0;
            d_QB[(nb + row) * 2 + 1] = s1;
        }
    }
}

// ---------------- U = QN_head @ Wk_head ----------------
__global__ void k_u(int dummy) {
    __shared__ __align__(16) unsigned sm[12288];
    unsigned* Ah = sm;
    unsigned* Al = sm + 2048;
    unsigned* Bh = sm + 4096;
    unsigned* Bl = sm + 8192;
    int nb = blockIdx.x * 64;
    int c0 = blockIdx.y * 128;
    int hh = blockIdx.z;
    int t = threadIdx.x;
    int w = t >> 5, lane = t & 31;
    int wm = w & 1, wn = w >> 1;
    int g = lane >> 2, tg = lane & 3;
    int arow = (lane & 7) + (((lane >> 3) & 1) << 3);
    int acsel = ((lane >> 4) << 2);
    int brow = (lane & 7) + ((lane >> 4) << 3);
    int bcsel = (((lane >> 3) & 1) << 2);
    unsigned AhB = (unsigned)__cvta_generic_to_shared(Ah);
    unsigned AlB = (unsigned)__cvta_generic_to_shared(Al);
    unsigned BhB = (unsigned)__cvta_generic_to_shared(Bh);
    unsigned BlB = (unsigned)__cvta_generic_to_shared(Bl);

    float acc[2][4][4];
#pragma unroll
    for (int mt = 0; mt < 2; mt++)
#pragma unroll
        for (int nt = 0; nt < 4; nt++)
#pragma unroll
            for (int q = 0; q < 4; q++) acc[mt][nt][q] = 0.f;

    for (int i = t; i < 64 * 16; i += 256) {
        int r = i >> 4, q = i & 15;
        float4 v = (nb + r < NDST)
            ? *(const float4*)&d_QN[(size_t)(nb + r) * DIM + hh * 64 + q * 4]
            : make_float4(0.f, 0.f, 0.f, 0.f);
        unsigned h0, l0, h1, l1;
        split2(make_float2(v.x, v.y), h0, l0);
        split2(make_float2(v.z, v.w), h1, l1);
        int off = SWZ(r, q * 2);
        Ah[off] = h0; Ah[off + 1] = h1; Al[off] = l0; Al[off + 1] = l1;
    }
    for (int i = t; i < 128 * 8; i += 256) {
        int r = i >> 3, q = i & 7;
        int gidx = (hh * 384 + c0 + r) * 32 + q * 4;
        uint4 vh = *(const uint4*)&d_WkBH[gidx];
        uint4 vl = *(const uint4*)&d_WkBL[gidx];
        int off = SWZ(r, q * 4);
        *(uint4*)&Bh[off] = vh; *(uint4*)&Bl[off] = vl;
    }
    __syncthreads();
#pragma unroll
    for (int s = 0; s < 4; s++) {
        int kp0 = s * 8;
        unsigned ah[2][4], al2[2][4], bh[4][2], bl[4][2];
#pragma unroll
        for (int mt = 0; mt < 2; mt++) {
            int r = wm * 32 + mt * 16 + arow;
            int c = kp0 + acsel;
            ldsm4(ah[mt], AhB + 4 * SWZ(r, c));
            ldsm4(al2[mt], AlB + 4 * SWZ(r, c));
        }
#pragma unroll
        for (int p = 0; p < 2; p++) {
            int r = wn * 32 + p * 16 + brow;
            int c = kp0 + bcsel;
            unsigned t4[4];
            ldsm4(t4, BhB + 4 * SWZ(r, c));
            bh[2 * p][0] = t4[0]; bh[2 * p][1] = t4[1];
            bh[2 * p + 1][0] = t4[2]; bh[2 * p + 1][1] = t4[3];
            ldsm4(t4, BlB + 4 * SWZ(r, c));
            bl[2 * p][0] = t4[0]; bl[2 * p][1] = t4[1];
            bl[2 * p + 1][0] = t4[2]; bl[2 * p + 1][1] = t4[3];
        }
#pragma unroll
        for (int mt = 0; mt < 2; mt++)
#pragma unroll
            for (int nt = 0; nt < 4; nt++) {
                mmabf(acc[mt][nt], ah[mt], bl[nt]);
                mmabf(acc[mt][nt], al2[mt], bh[nt]);
                mmabf(acc[mt][nt], ah[mt], bh[nt]);
            }
    }
#pragma unroll
    for (int mt = 0; mt < 2; mt++) {
        int r0 = nb + wm * 32 + mt * 16 + g, r1 = r0 + 8;
#pragma unroll
        for (int nt = 0; nt < 4; nt++) {
            int col = c0 + wn * 32 + nt * 8 + 2 * tg;
            if (col < DK) {
                if (r0 < NDST)
                    *(float2*)&d_U[(size_t)r0 * UW + hh * DK + col] =
                        make_float2(acc[mt][nt][0], acc[mt][nt][1]);
                if (r1 < NDST)
                    *(float2*)&d_U[(size_t)r1 * UW + hh * DK + col] =
                        make_float2(acc[mt][nt][2], acc[mt][nt][3]);
            }
        }
    }
}

// ---------------- warp-per-dst fused attention (3-ahead row prefetch) ----------------
__global__ void k_attn(const float* __restrict__ h, const float* __restrict__ f,
                       const float* __restrict__ w_t, const float* __restrict__ b_t) {
    int wid = blockIdx.x * 8 + (threadIdx.x >> 5);
    int l = threadIdx.x & 31;
    if (wid >= NDST) return;
    int n = wid;
    int start = d_starts[n];
    int cnt = d_counts[n];

    const float4 z4 = make_float4(0.f, 0.f, 0.f, 0.f);
    const float4* up = (const float4*)(d_U + (size_t)n * UW);
    float4 Ua0 = up[l], Ua1 = up[32 + l], Ua2 = (l < 25) ? up[64 + l] : z4;
    float4 Ub0 = up[89 + l], Ub1 = up[121 + l], Ub2 = (l < 25) ? up[153 + l] : z4;
    float4 Ta0 = z4, Ta1 = z4, Ta2 = z4, Tb0 = z4, Tb1 = z4, Tb2 = z4;

    float qb0 = d_QB[n * 2], qb1 = d_QB[n * 2 + 1];
    float4 tw = (l < 25) ? ((const float4*)w_t)[l] : z4;
    float4 tb = (l < 25) ? ((const float4*)b_t)[l] : z4;

    float ninf = __int_as_float(0xff800000);
    float m0 = ninf, m1 = ninf, s0 = 0.f, s1 = 0.f;

    // 3-ahead row prefetch
    float4 h0v = z4, f0v = z4, h1v = z4, f1v = z4, h2v = z4, f2v = z4;
    if (cnt > 0) {
        h0v = ((const float4*)(h + (size_t)d_src2[start] * DIM))[l];
        f0v = __ldcs(&((const float4*)(f + (size_t)d_order[start] * DIM))[l]);
    }
    if (cnt > 1) {
        h1v = ((const float4*)(h + (size_t)d_src2[start + 1] * DIM))[l];
        f1v = __ldcs(&((const float4*)(f + (size_t)d_order[start + 1] * DIM))[l]);
    }
    if (cnt > 2) {
        h2v = ((const float4*)(h + (size_t)d_src2[start + 2] * DIM))[l];
        f2v = __ldcs(&((const float4*)(f + (size_t)d_order[start + 2] * DIM))[l]);
    }

    for (int i = 0; i < cnt; i++) {
        float4 h3v = z4, f3v = z4;
        if (i + 3 < cnt) {
            h3v = ((const float4*)(h + (size_t)d_src2[start + i + 3] * DIM))[l];
            f3v = __ldcs(&((const float4*)(f + (size_t)d_order[start + i + 3] * DIM))[l]);
        }
        float dtc = d_dt2[start + i];

        float4 kvt = z4;
        if (l < 25) {
            float y, kk, rr;
            y = __fadd_rn(__fmul_rn(dtc, tw.x), tb.x);
            kk = rintf(y * INV2PI); rr = fmaf(-kk, PI2_A, y); rr = fmaf(kk, PI2_B, rr);
            kvt.x = __cosf(rr);
            y = __fadd_rn(__fmul_rn(dtc, tw.y), tb.y);
            kk = rintf(y * INV2PI); rr = fmaf(-kk, PI2_A, y); rr = fmaf(kk, PI2_B, rr);
            kvt.y = __cosf(rr);
            y = __fadd_rn(__fmul_rn(dtc, tw.z), tb.z);
            kk = rintf(y * INV2PI); rr = fmaf(-kk, PI2_A, y); rr = fmaf(kk, PI2_B, rr);
            kvt.z = __cosf(rr);
            y = __fadd_rn(__fmul_rn(dtc, tw.w), tb.w);
            kk = rintf(y * INV2PI); rr = fmaf(-kk, PI2_A, y); rr = fmaf(kk, PI2_B, rr);
            kvt.w = __cosf(rr);
        }

        float4 kvh = h0v, kvf = f0v;
        float sc0 = Ua0.x * kvh.x + Ua0.y * kvh.y + Ua0.z * kvh.z + Ua0.w * kvh.w;
        sc0 = fmaf(Ua1.x, kvf.x, sc0); sc0 = fmaf(Ua1.y, kvf.y, sc0);
        sc0 = fmaf(Ua1.z, kvf.z, sc0); sc0 = fmaf(Ua1.w, kvf.w, sc0);
        sc0 = fmaf(Ua2.x, kvt.x, sc0); sc0 = fmaf(Ua2.y, kvt.y, sc0);
        sc0 = fmaf(Ua2.z, kvt.z, sc0); sc0 = fmaf(Ua2.w, kvt.w, sc0);
        float sc1 = Ub0.x * kvh.x + Ub0.y * kvh.y + Ub0.z * kvh.z + Ub0.w * kvh.w;
        sc1 = fmaf(Ub1.x, kvf.x, sc1); sc1 = fmaf(Ub1.y, kvf.y, sc1);
        sc1 = fmaf(Ub1.z, kvf.z, sc1); sc1 = fmaf(Ub1.w, kvf.w, sc1);
        sc1 = fmaf(Ub2.x, kvt.x, sc1); sc1 = fmaf(Ub2.y, kvt.y, sc1);
        sc1 = fmaf(Ub2.z, kvt.z, sc1); sc1 = fmaf(Ub2.w, kvt.w, sc1);
#pragma unroll
        for (int o = 16; o > 0; o >>= 1) {
            sc0 += __shfl_xor_sync(0xffffffffu, sc0, o);
            sc1 += __shfl_xor_sync(0xffffffffu, sc1, o);
        }
        sc0 += qb0; sc1 += qb1;
        sc0 = sc0 >= 0.f ? sc0 : LEAKYC * sc0;
        sc1 = sc1 >= 0.f ? sc1 : LEAKYC * sc1;

        float nm0 = fmaxf(m0, sc0), nm1 = fmaxf(m1, sc1);
        float cr0 = __expf(m0 - nm0), cr1 = __expf(m1 - nm1);
        float e0x = __expf(sc0 - nm0), e1x = __expf(sc1 - nm1);
        s0 = s0 * cr0 + e0x;
        s1 = s1 * cr1 + e1x;
        Ta0.x = fmaf(Ta0.x, cr0, e0x * kvh.x); Ta0.y = fmaf(Ta0.y, cr0, e0x * kvh.y);
        Ta0.z = fmaf(Ta0.z, cr0, e0x * kvh.z); Ta0.w = fmaf(Ta0.w, cr0, e0x * kvh.w);
        Ta1.x = fmaf(Ta1.x, cr0, e0x * kvf.x); Ta1.y = fmaf(Ta1.y, cr0, e0x * kvf.y);
        Ta1.z = fmaf(Ta1.z, cr0, e0x * kvf.z); Ta1.w = fmaf(Ta1.w, cr0, e0x * kvf.w);
        Ta2.x = fmaf(Ta2.x, cr0, e0x * kvt.x); Ta2.y = fmaf(Ta2.y, cr0, e0x * kvt.y);
        Ta2.z = fmaf(Ta2.z, cr0, e0x * kvt.z); Ta2.w = fmaf(Ta2.w, cr0, e0x * kvt.w);
        Tb0.x = fmaf(Tb0.x, cr1, e1x * kvh.x); Tb0.y = fmaf(Tb0.y, cr1, e1x * kvh.y);
        Tb0.z = fmaf(Tb0.z, cr1, e1x * kvh.z); Tb0.w = fmaf(Tb0.w, cr1, e1x * kvh.w);
        Tb1.x = fmaf(Tb1.x, cr1, e1x * kvf.x); Tb1.y = fmaf(Tb1.y, cr1, e1x * kvf.y);
        Tb1.z = fmaf(Tb1.z, cr1, e1x * kvf.z); Tb1.w = fmaf(Tb1.w, cr1, e1x * kvf.w);
        Tb2.x = fmaf(Tb2.x, cr1, e1x * kvt.x); Tb2.y = fmaf(Tb2.y, cr1, e1x * kvt.y);
        Tb2.z = fmaf(Tb2.z, cr1, e1x * kvt.z); Tb2.w = fmaf(Tb2.w, cr1, e1x * kvt.w);
        m0 = nm0; m1 = nm1;

        h0v = h1v; f0v = f1v; h1v = h2v; f1v = f2v; h2v = h3v; f2v = f3v;
    }

    float r0 = s0 > 0.f ? 1.f / s0 : 0.f;
    float r1 = s1 > 0.f ? 1.f / s1 : 0.f;
    float4* tp = (float4*)(d_T + (size_t)n * UW);
    tp[l] = make_float4(Ta0.x * r0, Ta0.y * r0, Ta0.z * r0, Ta0.w * r0);
    tp[32 + l] = make_float4(Ta1.x * r0, Ta1.y * r0, Ta1.z * r0, Ta1.w * r0);
    if (l < 25) tp[64 + l] = make_float4(Ta2.x * r0, Ta2.y * r0, Ta2.z * r0, Ta2.w * r0);
    tp[89 + l] = make_float4(Tb0.x * r1, Tb0.y * r1, Tb0.z * r1, Tb0.w * r1);
    tp[121 + l] = make_float4(Tb1.x * r1, Tb1.y * r1, Tb1.z * r1, Tb1.w * r1);
    if (l < 25) tp[153 + l] = make_float4(Tb2.x * r1, Tb2.y * r1, Tb2.z * r1, Tb2.w * r1);
}

// ---------------- agg = T_head @ Wv_head^T + bv ----------------
__global__ void k_agg(const float* __restrict__ bv) {
    __shared__ __align__(16) unsigned sm[12288];
    unsigned* Ah = sm;
    unsigned* Al = sm + 4096;
    unsigned* Bh = sm + 8192;
    unsigned* Bl = sm + 10240;
    int nb = blockIdx.x * 128;
    int hh = blockIdx.y;
    int t = threadIdx.x;
    int w = t >> 5, lane = t & 31;
    int wm = w & 3, wn = w >> 2;
    int g = lane >> 2, tg = lane & 3;
    int arow = (lane & 7) + (((lane >> 3) & 1) << 3);
    int acsel = ((lane >> 4) << 2);
    int brow = (lane & 7) + ((lane >> 4) << 3);
    int bcsel = (((lane >> 3) & 1) << 2);
    unsigned AhB = (unsigned)__cvta_generic_to_shared(Ah);
    unsigned AlB = (unsigned)__cvta_generic_to_shared(Al);
    unsigned BhB = (unsigned)__cvta_generic_to_shared(Bh);
    unsigned BlB = (unsigned)__cvta_generic_to_shared(Bl);

    float acc[2][4][4];
#pragma unroll
    for (int mt = 0; mt < 2; mt++)
#pragma unroll
        for (int nt = 0; nt < 4; nt++)
#pragma unroll
            for (int q = 0; q < 4; q++) acc[mt][nt][q] = 0.f;

    for (int ch = 0; ch < 6; ch++) {
        for (int i = t; i < 128 * 16; i += 256) {
            int r = i >> 4, q = i & 15;
            int idx4 = ch * 16 + q;
            float4 v = make_float4(0.f, 0.f, 0.f, 0.f);
            if (nb + r < NDST && idx4 < 89) {
                const float* src = d_T + (size_t)(nb + r) * UW + hh * DK + idx4 * 4;
                float2 v01 = *(const float2*)src;
                float2 v23 = *(const float2*)(src + 2);
                v = make_float4(v01.x, v01.y, v23.x, v23.y);
            }
            unsigned h0, l0, h1, l1;
            split2(make_float2(v.x, v.y), h0, l0);
            split2(make_float2(v.z, v.w), h1, l1);
            int off = SWZ(r, q * 2);
            Ah[off] = h0; Ah[off + 1] = h1; Al[off] = l0; Al[off + 1] = l1;
        }
        for (int i = t; i < 64 * 8; i += 256) {
            int r = i >> 3, q = i & 7;
            int gidx = (hh * 64 + r) * 192 + ch * 32 + q * 4;
            uint4 vh = *(const uint4*)&d_WvBH[gidx];
            uint4 vl = *(const uint4*)&d_WvBL[gidx];
            int off = SWZ(r, q * 4);
            *(uint4*)&Bh[off] = vh; *(uint4*)&Bl[off] = vl;
        }
        __syncthreads();
#pragma unroll
        for (int s = 0; s < 4; s++) {
            int kp0 = s * 8;
            unsigned ah[2][4], al2[2][4], bh[4][2], bl[4][2];
#pragma unroll
            for (int mt = 0; mt < 2; mt++) {
                int r = wm * 32 + mt * 16 + arow;
                int c = kp0 + acsel;
                ldsm4(ah[mt], AhB + 4 * SWZ(r, c));
                ldsm4(al2[mt], AlB + 4 * SWZ(r, c));
            }
#pragma unroll
            for (int p = 0; p < 2; p++) {
                int r = wn * 32 + p * 16 + brow;
                int c = kp0 + bcsel;
                unsigned t4[4];
                ldsm4(t4, BhB + 4 * SWZ(r, c));
                bh[2 * p][0] = t4[0]; bh[2 * p][1] = t4[1];
                bh[2 * p + 1][0] = t4[2]; bh[2 * p + 1][1] = t4[3];
                ldsm4(t4, BlB + 4 * SWZ(r, c));
                bl[2 * p][0] = t4[0]; bl[2 * p][1] = t4[1];
                bl[2 * p + 1][0] = t4[2]; bl[2 * p + 1][1] = t4[3];
            }
#pragma unroll
            for (int mt = 0; mt < 2; mt++)
#pragma unroll
                for (int nt = 0; nt < 4; nt++) {
                    mmabf(acc[mt][nt], ah[mt], bl[nt]);
                    mmabf(acc[mt][nt], al2[mt], bh[nt]);
                    mmabf(acc[mt][nt], ah[mt], bh[nt]);
                }
        }
        __syncthreads();
    }
#pragma unroll
    for (int mt = 0; mt < 2; mt++) {
        int r0 = nb + wm * 32 + mt * 16 + g, r1 = r0 + 8;
        int has0 = (r0 < NDST) ? d_counts[r0] : 0;
        int has1 = (r1 < NDST) ? d_counts[r1] : 0;
#pragma unroll
        for (int nt = 0; nt < 4; nt++) {
            int col = hh * 64 + wn * 32 + nt * 8 + 2 * tg;
            float b0 = bv[col], b1 = bv[col + 1];
            if (r0 < NDST)
                *(float2*)&d_AGG[(size_t)r0 * DIM + col] = make_float2(
                    acc[mt][nt][0] + (has0 > 0 ? b0 : 0.f),
                    acc[mt][nt][1] + (has0 > 0 ? b1 : 0.f));
            if (r1 < NDST)
                *(float2*)&d_AGG[(size_t)r1 * DIM + col] = make_float2(
                    acc[mt][nt][2] + (has1 > 0 ? b0 : 0.f),
                    acc[mt][nt][3] + (has1 > 0 ? b1 : 0.f));
        }
    }
}

// ---------------- rst = relu([agg,h] @ Wout^T + bout) -> LayerNorm ----------------
__global__ void k_out(const float* __restrict__ h, const float* __restrict__ bout,
                      const float* __restrict__ ln_w, const float* __restrict__ ln_b,
                      float* __restrict__ out) {
    __shared__ __align__(16) unsigned sm[12288];
    unsigned* Ah = sm;
    unsigned* Al = sm + 2048;
    unsigned* Bh = sm + 4096;
    unsigned* Bl = sm + 8192;
    float* Rs = (float*)(sm + 4096);
    int nb = blockIdx.x * 64;
    int t = threadIdx.x;
    int w = t >> 5, lane = t & 31;
    int wm = w & 1, wn = w >> 1;
    int g = lane >> 2, tg = lane & 3;
    int arow = (lane & 7) + (((lane >> 3) & 1) << 3);
    int acsel = ((lane >> 4) << 2);
    int brow = (lane & 7) + ((lane >> 4) << 3);
    int bcsel = (((lane >> 3) & 1) << 2);
    unsigned AhB = (unsigned)__cvta_generic_to_shared(Ah);
    unsigned AlB = (unsigned)__cvta_generic_to_shared(Al);
    unsigned BhB = (unsigned)__cvta_generic_to_shared(Bh);
    unsigned BlB = (unsigned)__cvta_generic_to_shared(Bl);

    float acc[2][4][4];
#pragma unroll
    for (int mt = 0; mt < 2; mt++)
#pragma unroll
        for (int nt = 0; nt < 4; nt++)
#pragma unroll
            for (int q = 0; q < 4; q++) acc[mt][nt][q] = 0.f;

    for (int ch = 0; ch < 4; ch++) {
        const float* srcp = (ch < 2) ? (d_AGG + ch * 64) : (h + (ch - 2) * 64);
        for (int i = t; i < 64 * 16; i += 256) {
            int r = i >> 4, q = i & 15;
            float4 v = (nb + r < NDST)
                ? *(const float4*)&srcp[(size_t)(nb + r) * DIM + q * 4]
                : make_float4(0.f, 0.f, 0.f, 0.f);
            unsigned h0, l0, h1, l1;
            split2(make_float2(v.x, v.y), h0, l0);
            split2(make_float2(v.z, v.w), h1, l1);
            int off = SWZ(r, q * 2);
            Ah[off] = h0; Ah[off + 1] = h1; Al[off] = l0; Al[off + 1] = l1;
        }
        for (int i = t; i < 128 * 8; i += 256) {
            int r = i >> 3, q = i & 7;
            int gidx = r * 128 + ch * 32 + q * 4;
            uint4 vh = *(const uint4*)&d_WoBH[gidx];
            uint4 vl = *(const uint4*)&d_WoBL[gidx];
            int off = SWZ(r, q * 4);
            *(uint4*)&Bh[off] = vh; *(uint4*)&Bl[off] = vl;
        }
        __syncthreads();
#pragma unroll
        for (int s = 0; s < 4; s++) {
            int kp0 = s * 8;
            unsigned ah[2][4], al2[2][4], bh[4][2], bl[4][2];
#pragma unroll
            for (int mt = 0; mt < 2; mt++) {
                int r = wm * 32 + mt * 16 + arow;
                int c = kp0 + acsel;
                ldsm4(ah[mt], AhB + 4 * SWZ(r, c));
                ldsm4(al2[mt], AlB + 4 * SWZ(r, c));
            }
#pragma unroll
            for (int p = 0; p < 2; p++) {
                int r = wn * 32 + p * 16 + brow;
                int c = kp0 + bcsel;
                unsigned t4[4];
                ldsm4(t4, BhB + 4 * SWZ(r, c));
                bh[2 * p][0] = t4[0]; bh[2 * p][1] = t4[1];
                bh[2 * p + 1][0] = t4[2]; bh[2 * p + 1][1] = t4[3];
                ldsm4(t4, BlB + 4 * SWZ(r, c));
                bl[2 * p][0] = t4[0]; bl[2 * p][1] = t4[1];
                bl[2 * p + 1][0] = t4[2]; bl[2 * p + 1][1] = t4[3];
            }
#pragma unroll
            for (int mt = 0; mt < 2; mt++)
#pragma unroll
                for (int nt = 0; nt < 4; nt++) {
                    mmabf(acc[mt][nt], ah[mt], bl[nt]);
                    mmabf(acc[mt][nt], al2[mt], bh[nt]);
                    mmabf(acc[mt][nt], ah[mt], bh[nt]);
                }
        }
        __syncthreads();
    }

#pragma unroll
    for (int mt = 0; mt < 2; mt++) {
        int rl0 = wm * 32 + mt * 16 + g, rl1 = rl0 + 8;
#pragma unroll
        for (int nt = 0; nt < 4; nt++) {
            int col = wn * 32 + nt * 8 + 2 * tg;
            float b0 = bout[col], b1 = bout[col + 1];
            Rs[rl0 * 128 + col]     = fmaxf(acc[mt][nt][0] + b0, 0.f);
            Rs[rl0 * 128 + col + 1] = fmaxf(acc[mt][nt][1] + b1, 0.f);
            Rs[rl1 * 128 + col]     = fmaxf(acc[mt][nt][2] + b0, 0.f);
            Rs[rl1 * 128 + col + 1] = fmaxf(acc[mt][nt][3] + b1, 0.f);
        }
    }
    __syncthreads();

    int l = lane;
    float lw0 = ln_w[l], lw1 = ln_w[l + 32], lw2 = ln_w[l + 64], lw3 = ln_w[l + 96];
    float lb0 = ln_b[l], lb1 = ln_b[l + 32], lb2 = ln_b[l + 64], lb3 = ln_b[l + 96];
    for (int rr = 0; rr < 8; rr++) {
        int nl = w * 8 + rr;
        float v0 = Rs[nl * 128 + l], v1 = Rs[nl * 128 + l + 32];
        float v2 = Rs[nl * 128 + l + 64], v3 = Rs[nl * 128 + l + 96];
        float s = v0 + v1 + v2 + v3;
#pragma unroll
        for (int off = 16; off > 0; off >>= 1) s += __shfl_xor_sync(0xffffffffu, s, off);
        float mu = s * (1.f / 128.f);
        float d0 = v0 - mu, d1 = v1 - mu, d2 = v2 - mu, d3 = v3 - mu;
        float vs = d0 * d0 + d1 * d1 + d2 * d2 + d3 * d3;
#pragma unroll
        for (int off = 16; off > 0; off >>= 1) vs += __shfl_xor_sync(0xffffffffu, vs, off);
        float rstd = rsqrtf(vs * (1.f / 128.f) + EPSC);
        int ng = nb + nl;
        if (ng < NDST) {
            float* op = out + (size_t)ng * DIM;
            op[l] = d0 * rstd * lw0 + lb0;
            op[l + 32] = d1 * rstd * lw1 + lb1;
            op[l + 64] = d2 * rstd * lw2 + lb2;
            op[l + 96] = d3 * rstd * lw3 + lb3;
        }
    }
}

// ---------------- launch (fork/join, R10 structure) ----------------
extern "C" void kernel_launch(void* const* d_in, const int* in_sizes, int n_in,
                              void* d_out, int out_size) {
    const float* h       = (const float*)d_in[0];
    const float* f       = (const float*)d_in[1];
    const float* dt      = (const float*)d_in[2];
    const int*   src_idx = (const int*)d_in[3];
    const int*   dst_idx = (const int*)d_in[4];
    const float* w_t     = (const float*)d_in[5];
    const float* b_t     = (const float*)d_in[6];
    const float* Wq      = (const float*)d_in[7];
    const float* bq      = (const float*)d_in[8];
    const float* Wk      = (const float*)d_in[9];
    const float* bk      = (const float*)d_in[10];
    const float* Wv      = (const float*)d_in[11];
    const float* bv      = (const float*)d_in[12];
    const float* Wout    = (const float*)d_in[13];
    const float* bout    = (const float*)d_in[14];
    const float* ln_w    = (const float*)d_in[15];
    const float* ln_b    = (const float*)d_in[16];
    float* out = (float*)d_out;

    int E = in_sizes[2];
    int nch = (NDST + 511) / 512;
    int nb64 = (NDST + 63) / 64;
    int nb128 = (NDST + 127) / 128;

    static cudaStream_t s2 = nullptr;
    static cudaEvent_t evFork = nullptr, evJoin = nullptr;
    if (s2 == nullptr) {
        cudaStreamCreateWithFlags(&s2, cudaStreamNonBlocking);
        cudaEventCreateWithFlags(&evFork, cudaEventDisableTiming);
        cudaEventCreateWithFlags(&evJoin, cudaEventDisableTiming);
    }

    cudaEventRecord(evFork, 0);
    cudaStreamWaitEvent(s2, evFork, 0);

    // sort branch (s2)
    k_zero<<<(NDST + 255) / 256, 256, 0, s2>>>();
    k_hist<<<(E + 255) / 256, 256, 0, s2>>>(dst_idx, E);
    k_scan1<<<nch, 512, 0, s2>>>();
    k_scan3m<<<(NDST + 255) / 256, 256, 0, s2>>>();
    k_scatter<<<(E + 255) / 256, 256, 0, s2>>>(dst_idx, src_idx, dt, E);
    cudaEventRecord(evJoin, s2);

    // GEMM branch (default stream)
    k_prep<<<1, 128>>>(Wq, bq, b_t);
    k_wsplit<<<dim3(96, 4), 256>>>(Wq, Wk, Wv, Wout);
    k_q<<<nb64, 256>>>(h, bk);
    k_u<<<dim3(nb64, 3, 2), 256>>>(0);

    cudaStreamWaitEvent(0, evJoin, 0);
    k_attn<<<(NDST + 7) / 8, 256>>>(h, f, w_t, b_t);
    k_agg<<<dim3(nb128, 2), 256>>>(bv);
    k_out<<<nb64, 256>>>(h, bout, ln_w, ln_b, out);
}

// round 15
// speedup vs baseline: 1.5306x; 1.0838x over previous
#include <cuda_runtime.h>
#include <math.h>

#define NDST 25000
#define DIM 128
#define DT_DIM 100
#define DQ 228          // 128 + 100
#define DK 356          // 128 + 128 + 100
#define UW 712          // 2 heads * 356
#define EMAX 400000
#define LEAKYC 0.2f
#define EPSC 1e-5f

#define INV2PI 0.15915494309189535f
#define PI2_A  6.2831854820251465f
#define PI2_B  1.7484556000744415e-07f

// swizzled smem index: row stride 32 u32, 16B chunks xor'd by (r&7) -> ldmatrix-compatible
#define SWZ(r, kp) ((((r) << 5)) | (((kp) ^ (((r) & 7) << 2)) & 31))

// ---------------- device scratch ----------------
__device__ float d_cq[DIM];
__device__ float d_QB[NDST * 2];
__device__ int   d_counts[NDST];
__device__ int   d_starts[NDST];
__device__ int   d_incl[NDST];
__device__ int   d_csum[64];
__device__ int   d_rank[EMAX];
__device__ int   d_order[EMAX];
__device__ int   d_src2[EMAX];
__device__ float d_dt2[EMAX];
__device__ __align__(16) float d_U[(size_t)NDST * UW];
__device__ __align__(16) float d_T[(size_t)NDST * UW];
__device__ __align__(16) float d_QN[(size_t)NDST * DIM];
__device__ __align__(16) float d_AGG[(size_t)NDST * DIM];
__device__ __align__(16) unsigned d_WqBH[128 * 64],  d_WqBL[128 * 64];
__device__ __align__(16) unsigned d_WkBH[2 * 384 * 32], d_WkBL[2 * 384 * 32];
__device__ __align__(16) unsigned d_WvBH[2 * 64 * 192], d_WvBL[2 * 64 * 192];
__device__ __align__(16) unsigned d_WoBH[128 * 128], d_WoBL[128 * 128];

// ---------------- bf16 split / mma / ldmatrix / cp.async helpers ----------------
__device__ __forceinline__ void split2(float2 v, unsigned& hi, unsigned& lo) {
    unsigned h;
    asm("cvt.rn.bf16x2.f32 %0, %1, %2;" : "=r"(h) : "f"(v.y), "f"(v.x));
    float hx = __uint_as_float(h << 16);
    float hy = __uint_as_float(h & 0xffff0000u);
    float rx = v.x - hx, ry = v.y - hy;
    unsigned l;
    asm("cvt.rn.bf16x2.f32 %0, %1, %2;" : "=r"(l) : "f"(ry), "f"(rx));
    hi = h; lo = l;
}

__device__ __forceinline__ void mmabf(float* c, const unsigned* a, const unsigned* b) {
    asm volatile(
        "mma.sync.aligned.m16n8k16.row.col.f32.bf16.bf16.f32 "
        "{%0,%1,%2,%3},{%4,%5,%6,%7},{%8,%9},{%0,%1,%2,%3};"
        : "+f"(c[0]), "+f"(c[1]), "+f"(c[2]), "+f"(c[3])
        : "r"(a[0]), "r"(a[1]), "r"(a[2]), "r"(a[3]), "r"(b[0]), "r"(b[1]));
}

__device__ __forceinline__ void ldsm4(unsigned* r, unsigned addr) {
    asm volatile("ldmatrix.sync.aligned.m8n8.x4.shared.b16 {%0,%1,%2,%3}, [%4];"
        : "=r"(r[0]), "=r"(r[1]), "=r"(r[2]), "=r"(r[3]) : "r"(addr));
}

__device__ __forceinline__ void cpasync16(void* smem, const void* g) {
    unsigned saddr = (unsigned)__cvta_generic_to_shared(smem);
    asm volatile("cp.async.cg.shared.global [%0], [%1], 16;" :: "r"(saddr), "l"(g) : "memory");
}
__device__ __forceinline__ void cpcommit() {
    asm volatile("cp.async.commit_group;" ::: "memory");
}
__device__ __forceinline__ void cpwait3() {
    asm volatile("cp.async.wait_group 3;" ::: "memory");
}

// ---------------- tiny setup kernels ----------------
__global__ void k_zero() {
    int i = blockIdx.x * blockDim.x + threadIdx.x;
    if (i < NDST) d_counts[i] = 0;
}

__global__ void k_prep(const float* __restrict__ Wq, const float* __restrict__ bq,
                       const float* __restrict__ b_t) {
    int j = threadIdx.x;
    float s = bq[j];
    for (int t = 0; t < DT_DIM; t++)
        s = fmaf(Wq[j * DQ + DIM + t], cosf(b_t[t]), s);
    d_cq[j] = s;
}

__global__ void k_wsplit(const float* __restrict__ Wq, const float* __restrict__ Wk,
                         const float* __restrict__ Wv, const float* __restrict__ Wout) {
    int role = blockIdx.y;
    int idx = blockIdx.x * 256 + threadIdx.x;
    unsigned hi, lo;
    if (role == 0) {
        if (idx < 128 * 64) {
            int j = idx >> 6, kp = idx & 63;
            split2(make_float2(Wq[j * DQ + 2 * kp], Wq[j * DQ + 2 * kp + 1]), hi, lo);
            d_WqBH[idx] = hi; d_WqBL[idx] = lo;
        }
    } else if (role == 1) {
        if (idx < 2 * 384 * 32) {
            int hh = idx / 12288, rem = idx % 12288;
            int c = rem >> 5, kp = rem & 31;
            float2 v = make_float2(0.f, 0.f);
            if (c < DK) {
                v.x = Wk[(size_t)(hh * 64 + 2 * kp) * DK + c];
                v.y = Wk[(size_t)(hh * 64 + 2 * kp + 1) * DK + c];
            }
            split2(v, hi, lo);
            d_WkBH[idx] = hi; d_WkBL[idx] = lo;
        }
    } else if (role == 2) {
        if (idx < 2 * 64 * 192) {
            int hh = idx / 12288, rem = idx % 12288;
            int o = rem / 192, kp = rem % 192;
            float2 v = make_float2(0.f, 0.f);
            if (kp < 178) {
                v.x = Wv[(size_t)(hh * 64 + o) * DK + 2 * kp];
                v.y = Wv[(size_t)(hh * 64 + o) * DK + 2 * kp + 1];
            }
            split2(v, hi, lo);
            d_WvBH[idx] = hi; d_WvBL[idx] = lo;
        }
    } else {
        if (idx < 128 * 128) {
            int o = idx >> 7, kp = idx & 127;
            split2(make_float2(Wout[o * 256 + 2 * kp], Wout[o * 256 + 2 * kp + 1]), hi, lo);
            d_WoBH[idx] = hi; d_WoBL[idx] = lo;
        }
    }
}

// ---------------- counting sort ----------------
__global__ void k_hist(const int* __restrict__ dst, int E) {
    int e = blockIdx.x * blockDim.x + threadIdx.x;
    if (e < E) d_rank[e] = atomicAdd(&d_counts[dst[e]], 1);
}

__global__ void k_scan1() {
    __shared__ int sm[512];
    int b = blockIdx.x, t = threadIdx.x;
    int i = b * 512 + t;
    sm[t] = (i < NDST) ? d_counts[i] : 0;
    __syncthreads();
    for (int off = 1; off < 512; off <<= 1) {
        int x = (t >= off) ? sm[t - off] : 0;
        __syncthreads();
        sm[t] += x;
        __syncthreads();
    }
    if (i < NDST) d_incl[i] = sm[t];
    if (t == 511) d_csum[b] = sm[t];
}

__global__ void k_scan3m() {
    int i = blockIdx.x * blockDim.x + threadIdx.x;
    if (i < NDST) {
        int chunk = i >> 9;
        int off = 0;
        for (int b = 0; b < chunk; b++) off += d_csum[b];
        d_starts[i] = d_incl[i] - d_counts[i] + off;
    }
}

__global__ void k_scatter(const int* __restrict__ dst, const int* __restrict__ src,
                          const float* __restrict__ dtv, int E) {
    int e = blockIdx.x * blockDim.x + threadIdx.x;
    if (e < E) {
        int pos = d_starts[dst[e]] + d_rank[e];
        d_order[pos] = e;
        d_src2[pos] = src[e];
        d_dt2[pos] = dtv[e];
    }
}

// ---------------- qn = h @ WqT + cq  -> QN, QB ----------------
__global__ void k_q(const float* __restrict__ h, const float* __restrict__ bk) {
    __shared__ __align__(16) unsigned sm[12288];
    unsigned* Ah = sm;
    unsigned* Al = sm + 2048;
    unsigned* Bh = sm + 4096;
    unsigned* Bl = sm + 8192;
    int nb = blockIdx.x * 64;
    int t = threadIdx.x;
    int w = t >> 5, lane = t & 31;
    int wm = w & 1, wn = w >> 1;
    int g = lane >> 2, tg = lane & 3;
    int arow = (lane & 7) + (((lane >> 3) & 1) << 3);
    int acsel = ((lane >> 4) << 2);
    int brow = (lane & 7) + ((lane >> 4) << 3);
    int bcsel = (((lane >> 3) & 1) << 2);
    unsigned AhB = (unsigned)__cvta_generic_to_shared(Ah);
    unsigned AlB = (unsigned)__cvta_generic_to_shared(Al);
    unsigned BhB = (unsigned)__cvta_generic_to_shared(Bh);
    unsigned BlB = (unsigned)__cvta_generic_to_shared(Bl);

    float acc[2][4][4];
#pragma unroll
    for (int mt = 0; mt < 2; mt++)
#pragma unroll
        for (int nt = 0; nt < 4; nt++)
#pragma unroll
            for (int q = 0; q < 4; q++) acc[mt][nt][q] = 0.f;

    for (int ch = 0; ch < 2; ch++) {
        for (int i = t; i < 64 * 16; i += 256) {
            int r = i >> 4, q = i & 15;
            float4 v = (nb + r < NDST)
                ? *(const float4*)&h[(size_t)(nb + r) * DIM + ch * 64 + q * 4]
                : make_float4(0.f, 0.f, 0.f, 0.f);
            unsigned h0, l0, h1, l1;
            split2(make_float2(v.x, v.y), h0, l0);
            split2(make_float2(v.z, v.w), h1, l1);
            int off = SWZ(r, q * 2);
            Ah[off] = h0; Ah[off + 1] = h1; Al[off] = l0; Al[off + 1] = l1;
        }
        for (int i = t; i < 128 * 8; i += 256) {
            int r = i >> 3, q = i & 7;
            int gidx = r * 64 + ch * 32 + q * 4;
            uint4 vh = *(const uint4*)&d_WqBH[gidx];
            uint4 vl = *(const uint4*)&d_WqBL[gidx];
            int off = SWZ(r, q * 4);
            *(uint4*)&Bh[off] = vh; *(uint4*)&Bl[off] = vl;
        }
        __syncthreads();
#pragma unroll
        for (int s = 0; s < 4; s++) {
            int kp0 = s * 8;
            unsigned ah[2][4], al2[2][4], bh[4][2], bl[4][2];
#pragma unroll
            for (int mt = 0; mt < 2; mt++) {
                int r = wm * 32 + mt * 16 + arow;
                int c = kp0 + acsel;
                ldsm4(ah[mt], AhB + 4 * SWZ(r, c));
                ldsm4(al2[mt], AlB + 4 * SWZ(r, c));
            }
#pragma unroll
            for (int p = 0; p < 2; p++) {
                int r = wn * 32 + p * 16 + brow;
                int c = kp0 + bcsel;
                unsigned t4[4];
                ldsm4(t4, BhB + 4 * SWZ(r, c));
                bh[2 * p][0] = t4[0]; bh[2 * p][1] = t4[1];
                bh[2 * p + 1][0] = t4[2]; bh[2 * p + 1][1] = t4[3];
                ldsm4(t4, BlB + 4 * SWZ(r, c));
                bl[2 * p][0] = t4[0]; bl[2 * p][1] = t4[1];
                bl[2 * p + 1][0] = t4[2]; bl[2 * p + 1][1] = t4[3];
            }
#pragma unroll
            for (int mt = 0; mt < 2; mt++)
#pragma unroll
                for (int nt = 0; nt < 4; nt++) {
                    mmabf(acc[mt][nt], ah[mt], bl[nt]);
                    mmabf(acc[mt][nt], al2[mt], bh[nt]);
                    mmabf(acc[mt][nt], ah[mt], bh[nt]);
                }
        }
        __syncthreads();
    }
    float* Rs = (float*)sm;
#pragma unroll
    for (int mt = 0; mt < 2; mt++) {
        int rl0 = wm * 32 + mt * 16 + g, rl1 = rl0 + 8;
#pragma unroll
        for (int nt = 0; nt < 4; nt++) {
            int col = wn * 32 + nt * 8 + 2 * tg;
            float c0 = d_cq[col], c1 = d_cq[col + 1];
            Rs[rl0 * 128 + col]     = acc[mt][nt][0] + c0;
            Rs[rl0 * 128 + col + 1] = acc[mt][nt][1] + c1;
            Rs[rl1 * 128 + col]     = acc[mt][nt][2] + c0;
            Rs[rl1 * 128 + col + 1] = acc[mt][nt][3] + c1;
        }
    }
    __syncthreads();
    for (int i = t; i < 64 * 32; i += 256) {
        int r = i >> 5, c4 = i & 31;
        if (nb + r < NDST)
            *(float4*)&d_QN[(size_t)(nb + r) * DIM + c4 * 4] = *(const float4*)&Rs[r * 128 + c4 * 4];
    }
    float bk0 = bk[lane], bk1 = bk[lane + 32], bk2 = bk[lane + 64], bk3 = bk[lane + 96];
    for (int rr = 0; rr < 8; rr++) {
        int row = w * 8 + rr;
        float s0 = Rs[row * 128 + lane] * bk0 + Rs[row * 128 + lane + 32] * bk1;
        float s1 = Rs[row * 128 + lane + 64] * bk2 + Rs[row * 128 + lane + 96] * bk3;
#pragma unroll
        for (int o = 16; o > 0; o >>= 1) {
            s0 += __shfl_xor_sync(0xffffffffu, s0, o);
            s1 += __shfl_xor_sync(0xffffffffu, s1, o);
        }
        if (lane == 0 && nb + row < NDST) {
            d_QB[(nb + row) * 2] = s0;
            d_QB[(nb + row) * 2 + 1] = s1;
        }
    }
}

// ---------------- U = QN_head @ Wk_head ----------------
__global__ void k_u(int dummy) {
    __shared__ __align__(16) unsigned sm[12288];
    unsigned* Ah = sm;
    unsigned* Al = sm + 2048;
    unsigned* Bh = sm + 4096;
    unsigned* Bl = sm + 8192;
    int nb = blockIdx.x * 64;
    int c0 = blockIdx.y * 128;
    int hh = blockIdx.z;
    int t = threadIdx.x;
    int w = t >> 5, lane = t & 31;
    int wm = w & 1, wn = w >> 1;
    int g = lane >> 2, tg = lane & 3;
    int arow = (lane & 7) + (((lane >> 3) & 1) << 3);
    int acsel = ((lane >> 4) << 2);
    int brow = (lane & 7) + ((lane >> 4) << 3);
    int bcsel = (((lane >> 3) & 1) << 2);
    unsigned AhB = (unsigned)__cvta_generic_to_shared(Ah);
    unsigned AlB = (unsigned)__cvta_generic_to_shared(Al);
    unsigned BhB = (unsigned)__cvta_generic_to_shared(Bh);
    unsigned BlB = (unsigned)__cvta_generic_to_shared(Bl);

    float acc[2][4][4];
#pragma unroll
    for (int mt = 0; mt < 2; mt++)
#pragma unroll
        for (int nt = 0; nt < 4; nt++)
#pragma unroll
            for (int q = 0; q < 4; q++) acc[mt][nt][q] = 0.f;

    for (int i = t; i < 64 * 16; i += 256) {
        int r = i >> 4, q = i & 15;
        float4 v = (nb + r < NDST)
            ? *(const float4*)&d_QN[(size_t)(nb + r) * DIM + hh * 64 + q * 4]
            : make_float4(0.f, 0.f, 0.f, 0.f);
        unsigned h0, l0, h1, l1;
        split2(make_float2(v.x, v.y), h0, l0);
        split2(make_float2(v.z, v.w), h1, l1);
        int off = SWZ(r, q * 2);
        Ah[off] = h0; Ah[off + 1] = h1; Al[off] = l0; Al[off + 1] = l1;
    }
    for (int i = t; i < 128 * 8; i += 256) {
        int r = i >> 3, q = i & 7;
        int gidx = (hh * 384 + c0 + r) * 32 + q * 4;
        uint4 vh = *(const uint4*)&d_WkBH[gidx];
        uint4 vl = *(const uint4*)&d_WkBL[gidx];
        int off = SWZ(r, q * 4);
        *(uint4*)&Bh[off] = vh; *(uint4*)&Bl[off] = vl;
    }
    __syncthreads();
#pragma unroll
    for (int s = 0; s < 4; s++) {
        int kp0 = s * 8;
        unsigned ah[2][4], al2[2][4], bh[4][2], bl[4][2];
#pragma unroll
        for (int mt = 0; mt < 2; mt++) {
            int r = wm * 32 + mt * 16 + arow;
            int c = kp0 + acsel;
            ldsm4(ah[mt], AhB + 4 * SWZ(r, c));
            ldsm4(al2[mt], AlB + 4 * SWZ(r, c));
        }
#pragma unroll
        for (int p = 0; p < 2; p++) {
            int r = wn * 32 + p * 16 + brow;
            int c = kp0 + bcsel;
            unsigned t4[4];
            ldsm4(t4, BhB + 4 * SWZ(r, c));
            bh[2 * p][0] = t4[0]; bh[2 * p][1] = t4[1];
            bh[2 * p + 1][0] = t4[2]; bh[2 * p + 1][1] = t4[3];
            ldsm4(t4, BlB + 4 * SWZ(r, c));
            bl[2 * p][0] = t4[0]; bl[2 * p][1] = t4[1];
            bl[2 * p + 1][0] = t4[2]; bl[2 * p + 1][1] = t4[3];
        }
#pragma unroll
        for (int mt = 0; mt < 2; mt++)
#pragma unroll
            for (int nt = 0; nt < 4; nt++) {
                mmabf(acc[mt][nt], ah[mt], bl[nt]);
                mmabf(acc[mt][nt], al2[mt], bh[nt]);
                mmabf(acc[mt][nt], ah[mt], bh[nt]);
            }
    }
#pragma unroll
    for (int mt = 0; mt < 2; mt++) {
        int r0 = nb + wm * 32 + mt * 16 + g, r1 = r0 + 8;
#pragma unroll
        for (int nt = 0; nt < 4; nt++) {
            int col = c0 + wn * 32 + nt * 8 + 2 * tg;
            if (col < DK) {
                if (r0 < NDST)
                    *(float2*)&d_U[(size_t)r0 * UW + hh * DK + col] =
                        make_float2(acc[mt][nt][0], acc[mt][nt][1]);
                if (r1 < NDST)
                    *(float2*)&d_U[(size_t)r1 * UW + hh * DK + col] =
                        make_float2(acc[mt][nt][2], acc[mt][nt][3]);
            }
        }
    }
}

// ---------------- warp-per-dst fused attention (cp.async 4-stage smem ring) ----------------
__global__ void k_attn(const float* __restrict__ h, const float* __restrict__ f,
                       const float* __restrict__ w_t, const float* __restrict__ b_t) {
    __shared__ __align__(16) float4 stg[8][4][2][32];   // warp, stage, {h,f}, lane : 32 KB
    int w = threadIdx.x >> 5;
    int l = threadIdx.x & 31;
    int wid = blockIdx.x * 8 + w;
    if (wid >= NDST) return;
    int n = wid;
    int start = d_starts[n];
    int cnt = d_counts[n];

    const float4 z4 = make_float4(0.f, 0.f, 0.f, 0.f);
    const float4* up = (const float4*)(d_U + (size_t)n * UW);
    float4 Ua0 = up[l], Ua1 = up[32 + l], Ua2 = (l < 25) ? up[64 + l] : z4;
    float4 Ub0 = up[89 + l], Ub1 = up[121 + l], Ub2 = (l < 25) ? up[153 + l] : z4;
    float4 Ta0 = z4, Ta1 = z4, Ta2 = z4, Tb0 = z4, Tb1 = z4, Tb2 = z4;

    float qb0 = d_QB[n * 2], qb1 = d_QB[n * 2 + 1];
    float4 tw = (l < 25) ? ((const float4*)w_t)[l] : z4;
    float4 tb = (l < 25) ? ((const float4*)b_t)[l] : z4;

    float ninf = __int_as_float(0xff800000);
    float m0 = ninf, m1 = ninf, s0 = 0.f, s1 = 0.f;

    // prologue: stages 0..2
#pragma unroll
    for (int p = 0; p < 3; p++) {
        if (p < cnt) {
            cpasync16(&stg[w][p][0][l], h + (size_t)d_src2[start + p] * DIM + l * 4);
            cpasync16(&stg[w][p][1][l], f + (size_t)d_order[start + p] * DIM + l * 4);
        }
        cpcommit();
    }

    for (int i = 0; i < cnt; i++) {
        // issue stage i+3
        int sl = (i + 3) & 3;
        if (i + 3 < cnt) {
            cpasync16(&stg[w][sl][0][l], h + (size_t)d_src2[start + i + 3] * DIM + l * 4);
            cpasync16(&stg[w][sl][1][l], f + (size_t)d_order[start + i + 3] * DIM + l * 4);
        }
        cpcommit();
        cpwait3();                 // stage i resident (own-lane bytes)

        float dtc = d_dt2[start + i];
        float4 kvt = z4;
        if (l < 25) {
            float y, kk, rr;
            y = __fadd_rn(__fmul_rn(dtc, tw.x), tb.x);
            kk = rintf(y * INV2PI); rr = fmaf(-kk, PI2_A, y); rr = fmaf(kk, PI2_B, rr);
            kvt.x = __cosf(rr);
            y = __fadd_rn(__fmul_rn(dtc, tw.y), tb.y);
            kk = rintf(y * INV2PI); rr = fmaf(-kk, PI2_A, y); rr = fmaf(kk, PI2_B, rr);
            kvt.y = __cosf(rr);
            y = __fadd_rn(__fmul_rn(dtc, tw.z), tb.z);
            kk = rintf(y * INV2PI); rr = fmaf(-kk, PI2_A, y); rr = fmaf(kk, PI2_B, rr);
            kvt.z = __cosf(rr);
            y = __fadd_rn(__fmul_rn(dtc, tw.w), tb.w);
            kk = rintf(y * INV2PI); rr = fmaf(-kk, PI2_A, y); rr = fmaf(kk, PI2_B, rr);
            kvt.w = __cosf(rr);
        }

        int sc = i & 3;
        float4 kvh = stg[w][sc][0][l];
        float4 kvf = stg[w][sc][1][l];

        float sc0 = Ua0.x * kvh.x + Ua0.y * kvh.y + Ua0.z * kvh.z + Ua0.w * kvh.w;
        sc0 = fmaf(Ua1.x, kvf.x, sc0); sc0 = fmaf(Ua1.y, kvf.y, sc0);
        sc0 = fmaf(Ua1.z, kvf.z, sc0); sc0 = fmaf(Ua1.w, kvf.w, sc0);
        sc0 = fmaf(Ua2.x, kvt.x, sc0); sc0 = fmaf(Ua2.y, kvt.y, sc0);
        sc0 = fmaf(Ua2.z, kvt.z, sc0); sc0 = fmaf(Ua2.w, kvt.w, sc0);
        float sc1 = Ub0.x * kvh.x + Ub0.y * kvh.y + Ub0.z * kvh.z + Ub0.w * kvh.w;
        sc1 = fmaf(Ub1.x, kvf.x, sc1); sc1 = fmaf(Ub1.y, kvf.y, sc1);
        sc1 = fmaf(Ub1.z, kvf.z, sc1); sc1 = fmaf(Ub1.w, kvf.w, sc1);
        sc1 = fmaf(Ub2.x, kvt.x, sc1); sc1 = fmaf(Ub2.y, kvt.y, sc1);
        sc1 = fmaf(Ub2.z, kvt.z, sc1); sc1 = fmaf(Ub2.w, kvt.w, sc1);
#pragma unroll
        for (int o = 16; o > 0; o >>= 1) {
            sc0 += __shfl_xor_sync(0xffffffffu, sc0, o);
            sc1 += __shfl_xor_sync(0xffffffffu, sc1, o);
        }
        sc0 += qb0; sc1 += qb1;
        sc0 = sc0 >= 0.f ? sc0 : LEAKYC * sc0;
        sc1 = sc1 >= 0.f ? sc1 : LEAKYC * sc1;

        float nm0 = fmaxf(m0, sc0), nm1 = fmaxf(m1, sc1);
        float cr0 = __expf(m0 - nm0), cr1 = __expf(m1 - nm1);
        float e0x = __expf(sc0 - nm0), e1x = __expf(sc1 - nm1);
        s0 = s0 * cr0 + e0x;
        s1 = s1 * cr1 + e1x;
        Ta0.x = fmaf(Ta0.x, cr0, e0x * kvh.x); Ta0.y = fmaf(Ta0.y, cr0, e0x * kvh.y);
        Ta0.z = fmaf(Ta0.z, cr0, e0x * kvh.z); Ta0.w = fmaf(Ta0.w, cr0, e0x * kvh.w);
        Ta1.x = fmaf(Ta1.x, cr0, e0x * kvf.x); Ta1.y = fmaf(Ta1.y, cr0, e0x * kvf.y);
        Ta1.z = fmaf(Ta1.z, cr0, e0x * kvf.z); Ta1.w = fmaf(Ta1.w, cr0, e0x * kvf.w);
        Ta2.x = fmaf(Ta2.x, cr0, e0x * kvt.x); Ta2.y = fmaf(Ta2.y, cr0, e0x * kvt.y);
        Ta2.z = fmaf(Ta2.z, cr0, e0x * kvt.z); Ta2.w = fmaf(Ta2.w, cr0, e0x * kvt.w);
        Tb0.x = fmaf(Tb0.x, cr1, e1x * kvh.x); Tb0.y = fmaf(Tb0.y, cr1, e1x * kvh.y);
        Tb0.z = fmaf(Tb0.z, cr1, e1x * kvh.z); Tb0.w = fmaf(Tb0.w, cr1, e1x * kvh.w);
        Tb1.x = fmaf(Tb1.x, cr1, e1x * kvf.x); Tb1.y = fmaf(Tb1.y, cr1, e1x * kvf.y);
        Tb1.z = fmaf(Tb1.z, cr1, e1x * kvf.z); Tb1.w = fmaf(Tb1.w, cr1, e1x * kvf.w);
        Tb2.x = fmaf(Tb2.x, cr1, e1x * kvt.x); Tb2.y = fmaf(Tb2.y, cr1, e1x * kvt.y);
        Tb2.z = fmaf(Tb2.z, cr1, e1x * kvt.z); Tb2.w = fmaf(Tb2.w, cr1, e1x * kvt.w);
        m0 = nm0; m1 = nm1;
    }

    float r0 = s0 > 0.f ? 1.f / s0 : 0.f;
    float r1 = s1 > 0.f ? 1.f / s1 : 0.f;
    float4* tp = (float4*)(d_T + (size_t)n * UW);
    tp[l] = make_float4(Ta0.x * r0, Ta0.y * r0, Ta0.z * r0, Ta0.w * r0);
    tp[32 + l] = make_float4(Ta1.x * r0, Ta1.y * r0, Ta1.z * r0, Ta1.w * r0);
    if (l < 25) tp[64 + l] = make_float4(Ta2.x * r0, Ta2.y * r0, Ta2.z * r0, Ta2.w * r0);
    tp[89 + l] = make_float4(Tb0.x * r1, Tb0.y * r1, Tb0.z * r1, Tb0.w * r1);
    tp[121 + l] = make_float4(Tb1.x * r1, Tb1.y * r1, Tb1.z * r1, Tb1.w * r1);
    if (l < 25) tp[153 + l] = make_float4(Tb2.x * r1, Tb2.y * r1, Tb2.z * r1, Tb2.w * r1);
}

// ---------------- agg = T_head @ Wv_head^T + bv ----------------
__global__ void k_agg(const float* __restrict__ bv) {
    __shared__ __align__(16) unsigned sm[12288];
    unsigned* Ah = sm;
    unsigned* Al = sm + 4096;
    unsigned* Bh = sm + 8192;
    unsigned* Bl = sm + 10240;
    int nb = blockIdx.x * 128;
    int hh = blockIdx.y;
    int t = threadIdx.x;
    int w = t >> 5, lane = t & 31;
    int wm = w & 3, wn = w >> 2;
    int g = lane >> 2, tg = lane & 3;
    int arow = (lane & 7) + (((lane >> 3) & 1) << 3);
    int acsel = ((lane >> 4) << 2);
    int brow = (lane & 7) + ((lane >> 4) << 3);
    int bcsel = (((lane >> 3) & 1) << 2);
    unsigned AhB = (unsigned)__cvta_generic_to_shared(Ah);
    unsigned AlB = (unsigned)__cvta_generic_to_shared(Al);
    unsigned BhB = (unsigned)__cvta_generic_to_shared(Bh);
    unsigned BlB = (unsigned)__cvta_generic_to_shared(Bl);

    float acc[2][4][4];
#pragma unroll
    for (int mt = 0; mt < 2; mt++)
#pragma unroll
        for (int nt = 0; nt < 4; nt++)
#pragma unroll
            for (int q = 0; q < 4; q++) acc[mt][nt][q] = 0.f;

    for (int ch = 0; ch < 6; ch++) {
        for (int i = t; i < 128 * 16; i += 256) {
            int r = i >> 4, q = i & 15;
            int idx4 = ch * 16 + q;
            float4 v = make_float4(0.f, 0.f, 0.f, 0.f);
            if (nb + r < NDST && idx4 < 89) {
                const float* src = d_T + (size_t)(nb + r) * UW + hh * DK + idx4 * 4;
                float2 v01 = *(const float2*)src;
                float2 v23 = *(const float2*)(src + 2);
                v = make_float4(v01.x, v01.y, v23.x, v23.y);
            }
            unsigned h0, l0, h1, l1;
            split2(make_float2(v.x, v.y), h0, l0);
            split2(make_float2(v.z, v.w), h1, l1);
            int off = SWZ(r, q * 2);
            Ah[off] = h0; Ah[off + 1] = h1; Al[off] = l0; Al[off + 1] = l1;
        }
        for (int i = t; i < 64 * 8; i += 256) {
            int r = i >> 3, q = i & 7;
            int gidx = (hh * 64 + r) * 192 + ch * 32 + q * 4;
            uint4 vh = *(const uint4*)&d_WvBH[gidx];
            uint4 vl = *(const uint4*)&d_WvBL[gidx];
            int off = SWZ(r, q * 4);
            *(uint4*)&Bh[off] = vh; *(uint4*)&Bl[off] = vl;
        }
        __syncthreads();
#pragma unroll
        for (int s = 0; s < 4; s++) {
            int kp0 = s * 8;
            unsigned ah[2][4], al2[2][4], bh[4][2], bl[4][2];
#pragma unroll
            for (int mt = 0; mt < 2; mt++) {
                int r = wm * 32 + mt * 16 + arow;
                int c = kp0 + acsel;
                ldsm4(ah[mt], AhB + 4 * SWZ(r, c));
                ldsm4(al2[mt], AlB + 4 * SWZ(r, c));
            }
#pragma unroll
            for (int p = 0; p < 2; p++) {
                int r = wn * 32 + p * 16 + brow;
                int c = kp0 + bcsel;
                unsigned t4[4];
                ldsm4(t4, BhB + 4 * SWZ(r, c));
                bh[2 * p][0] = t4[0]; bh[2 * p][1] = t4[1];
                bh[2 * p + 1][0] = t4[2]; bh[2 * p + 1][1] = t4[3];
                ldsm4(t4, BlB + 4 * SWZ(r, c));
                bl[2 * p][0] = t4[0]; bl[2 * p][1] = t4[1];
                bl[2 * p + 1][0] = t4[2]; bl[2 * p + 1][1] = t4[3];
            }
#pragma unroll
            for (int mt = 0; mt < 2; mt++)
#pragma unroll
                for (int nt = 0; nt < 4; nt++) {
                    mmabf(acc[mt][nt], ah[mt], bl[nt]);
                    mmabf(acc[mt][nt], al2[mt], bh[nt]);
                    mmabf(acc[mt][nt], ah[mt], bh[nt]);
                }
        }
        __syncthreads();
    }
#pragma unroll
    for (int mt = 0; mt < 2; mt++) {
        int r0 = nb + wm * 32 + mt * 16 + g, r1 = r0 + 8;
        int has0 = (r0 < NDST) ? d_counts[r0] : 0;
        int has1 = (r1 < NDST) ? d_counts[r1] : 0;
#pragma unroll
        for (int nt = 0; nt < 4; nt++) {
            int col = hh * 64 + wn * 32 + nt * 8 + 2 * tg;
            float b0 = bv[col], b1 = bv[col + 1];
            if (r0 < NDST)
                *(float2*)&d_AGG[(size_t)r0 * DIM + col] = make_float2(
                    acc[mt][nt][0] + (has0 > 0 ? b0 : 0.f),
                    acc[mt][nt][1] + (has0 > 0 ? b1 : 0.f));
            if (r1 < NDST)
                *(float2*)&d_AGG[(size_t)r1 * DIM + col] = make_float2(
                    acc[mt][nt][2] + (has1 > 0 ? b0 : 0.f),
                    acc[mt][nt][3] + (has1 > 0 ? b1 : 0.f));
        }
    }
}

// ---------------- rst = relu([agg,h] @ Wout^T + bout) -> LayerNorm ----------------
__global__ void k_out(const float* __restrict__ h, const float* __restrict__ bout,
                      const float* __restrict__ ln_w, const float* __restrict__ ln_b,
                      float* __restrict__ out) {
    __shared__ __align__(16) unsigned sm[12288];
    unsigned* Ah = sm;
    unsigned* Al = sm + 2048;
    unsigned* Bh = sm + 4096;
    unsigned* Bl = sm + 8192;
    float* Rs = (float*)(sm + 4096);
    int nb = blockIdx.x * 64;
    int t = threadIdx.x;
    int w = t >> 5, lane = t & 31;
    int wm = w & 1, wn = w >> 1;
    int g = lane >> 2, tg = lane & 3;
    int arow = (lane & 7) + (((lane >> 3) & 1) << 3);
    int acsel = ((lane >> 4) << 2);
    int brow = (lane & 7) + ((lane >> 4) << 3);
    int bcsel = (((lane >> 3) & 1) << 2);
    unsigned AhB = (unsigned)__cvta_generic_to_shared(Ah);
    unsigned AlB = (unsigned)__cvta_generic_to_shared(Al);
    unsigned BhB = (unsigned)__cvta_generic_to_shared(Bh);
    unsigned BlB = (unsigned)__cvta_generic_to_shared(Bl);

    float acc[2][4][4];
#pragma unroll
    for (int mt = 0; mt < 2; mt++)
#pragma unroll
        for (int nt = 0; nt < 4; nt++)
#pragma unroll
            for (int q = 0; q < 4; q++) acc[mt][nt][q] = 0.f;

    for (int ch = 0; ch < 4; ch++) {
        const float* srcp = (ch < 2) ? (d_AGG + ch * 64) : (h + (ch - 2) * 64);
        for (int i = t; i < 64 * 16; i += 256) {
            int r = i >> 4, q = i & 15;
            float4 v = (nb + r < NDST)
                ? *(const float4*)&srcp[(size_t)(nb + r) * DIM + q * 4]
                : make_float4(0.f, 0.f, 0.f, 0.f);
            unsigned h0, l0, h1, l1;
            split2(make_float2(v.x, v.y), h0, l0);
            split2(make_float2(v.z, v.w), h1, l1);
            int off = SWZ(r, q * 2);
            Ah[off] = h0; Ah[off + 1] = h1; Al[off] = l0; Al[off + 1] = l1;
        }
        for (int i = t; i < 128 * 8; i += 256) {
            int r = i >> 3, q = i & 7;
            int gidx = r * 128 + ch * 32 + q * 4;
            uint4 vh = *(const uint4*)&d_WoBH[gidx];
            uint4 vl = *(const uint4*)&d_WoBL[gidx];
            int off = SWZ(r, q * 4);
            *(uint4*)&Bh[off] = vh; *(uint4*)&Bl[off] = vl;
        }
        __syncthreads();
#pragma unroll
        for (int s = 0; s < 4; s++) {
            int kp0 = s * 8;
            unsigned ah[2][4], al2[2][4], bh[4][2], bl[4][2];
#pragma unroll
            for (int mt = 0; mt < 2; mt++) {
                int r = wm * 32 + mt * 16 + arow;
                int c = kp0 + acsel;
                ldsm4(ah[mt], AhB + 4 * SWZ(r, c));
                ldsm4(al2[mt], AlB + 4 * SWZ(r, c));
            }
#pragma unroll
            for (int p = 0; p < 2; p++) {
                int r = wn * 32 + p * 16 + brow;
                int c = kp0 + bcsel;
                unsigned t4[4];
                ldsm4(t4, BhB + 4 * SWZ(r, c));
                bh[2 * p][0] = t4[0]; bh[2 * p][1] = t4[1];
                bh[2 * p + 1][0] = t4[2]; bh[2 * p + 1][1] = t4[3];
                ldsm4(t4, BlB + 4 * SWZ(r, c));
                bl[2 * p][0] = t4[0]; bl[2 * p][1] = t4[1];
                bl[2 * p + 1][0] = t4[2]; bl[2 * p + 1][1] = t4[3];
            }
#pragma unroll
            for (int mt = 0; mt < 2; mt++)
#pragma unroll
                for (int nt = 0; nt < 4; nt++) {
                    mmabf(acc[mt][nt], ah[mt], bl[nt]);
                    mmabf(acc[mt][nt], al2[mt], bh[nt]);
                    mmabf(acc[mt][nt], ah[mt], bh[nt]);
                }
        }
        __syncthreads();
    }

#pragma unroll
    for (int mt = 0; mt < 2; mt++) {
        int rl0 = wm * 32 + mt * 16 + g, rl1 = rl0 + 8;
#pragma unroll
        for (int nt = 0; nt < 4; nt++) {
            int col = wn * 32 + nt * 8 + 2 * tg;
            float b0 = bout[col], b1 = bout[col + 1];
            Rs[rl0 * 128 + col]     = fmaxf(acc[mt][nt][0] + b0, 0.f);
            Rs[rl0 * 128 + col + 1] = fmaxf(acc[mt][nt][1] + b1, 0.f);
            Rs[rl1 * 128 + col]     = fmaxf(acc[mt][nt][2] + b0, 0.f);
            Rs[rl1 * 128 + col + 1] = fmaxf(acc[mt][nt][3] + b1, 0.f);
        }
    }
    __syncthreads();

    int l = lane;
    float lw0 = ln_w[l], lw1 = ln_w[l + 32], lw2 = ln_w[l + 64], lw3 = ln_w[l + 96];
    float lb0 = ln_b[l], lb1 = ln_b[l + 32], lb2 = ln_b[l + 64], lb3 = ln_b[l + 96];
    for (int rr = 0; rr < 8; rr++) {
        int nl = w * 8 + rr;
        float v0 = Rs[nl * 128 + l], v1 = Rs[nl * 128 + l + 32];
        float v2 = Rs[nl * 128 + l + 64], v3 = Rs[nl * 128 + l + 96];
        float s = v0 + v1 + v2 + v3;
#pragma unroll
        for (int off = 16; off > 0; off >>= 1) s += __shfl_xor_sync(0xffffffffu, s, off);
        float mu = s * (1.f / 128.f);
        float d0 = v0 - mu, d1 = v1 - mu, d2 = v2 - mu, d3 = v3 - mu;
        float vs = d0 * d0 + d1 * d1 + d2 * d2 + d3 * d3;
#pragma unroll
        for (int off = 16; off > 0; off >>= 1) vs += __shfl_xor_sync(0xffffffffu, vs, off);
        float rstd = rsqrtf(vs * (1.f / 128.f) + EPSC);
        int ng = nb + nl;
        if (ng < NDST) {
            float* op = out + (size_t)ng * DIM;
            op[l] = d0 * rstd * lw0 + lb0;
            op[l + 32] = d1 * rstd * lw1 + lb1;
            op[l + 64] = d2 * rstd * lw2 + lb2;
            op[l + 96] = d3 * rstd * lw3 + lb3;
        }
    }
}

// ---------------- launch (fork/join, R10 structure) ----------------
extern "C" void kernel_launch(void* const* d_in, const int* in_sizes, int n_in,
                              void* d_out, int out_size) {
    const float* h       = (const float*)d_in[0];
    const float* f       = (const float*)d_in[1];
    const float* dt      = (const float*)d_in[2];
    const int*   src_idx = (const int*)d_in[3];
    const int*   dst_idx = (const int*)d_in[4];
    const float* w_t     = (const float*)d_in[5];
    const float* b_t     = (const float*)d_in[6];
    const float* Wq      = (const float*)d_in[7];
    const float* bq      = (const float*)d_in[8];
    const float* Wk      = (const float*)d_in[9];
    const float* bk      = (const float*)d_in[10];
    const float* Wv      = (const float*)d_in[11];
    const float* bv      = (const float*)d_in[12];
    const float* Wout    = (const float*)d_in[13];
    const float* bout    = (const float*)d_in[14];
    const float* ln_w    = (const float*)d_in[15];
    const float* ln_b    = (const float*)d_in[16];
    float* out = (float*)d_out;

    int E = in_sizes[2];
    int nch = (NDST + 511) / 512;
    int nb64 = (NDST + 63) / 64;
    int nb128 = (NDST + 127) / 128;

    static cudaStream_t s2 = nullptr;
    static cudaEvent_t evFork = nullptr, evJoin = nullptr;
    if (s2 == nullptr) {
        cudaStreamCreateWithFlags(&s2, cudaStreamNonBlocking);
        cudaEventCreateWithFlags(&evFork, cudaEventDisableTiming);
        cudaEventCreateWithFlags(&evJoin, cudaEventDisableTiming);
    }

    cudaEventRecord(evFork, 0);
    cudaStreamWaitEvent(s2, evFork, 0);

    // sort branch (s2)
    k_zero<<<(NDST + 255) / 256, 256, 0, s2>>>();
    k_hist<<<(E + 255) / 256, 256, 0, s2>>>(dst_idx, E);
    k_scan1<<<nch, 512, 0, s2>>>();
    k_scan3m<<<(NDST + 255) / 256, 256, 0, s2>>>();
    k_scatter<<<(E + 255) / 256, 256, 0, s2>>>(dst_idx, src_idx, dt, E);
    cudaEventRecord(evJoin, s2);

    // GEMM branch (default stream)
    k_prep<<<1, 128>>>(Wq, bq, b_t);
    k_wsplit<<<dim3(96, 4), 256>>>(Wq, Wk, Wv, Wout);
    k_q<<<nb64, 256>>>(h, bk);
    k_u<<<dim3(nb64, 3, 2), 256>>>(0);

    cudaStreamWaitEvent(0, evJoin, 0);
    k_attn<<<(NDST + 7) / 8, 256>>>(h, f, w_t, b_t);
    k_agg<<<dim3(nb128, 2), 256>>>(bv);
    k_out<<<nb64, 256>>>(h, bout, ln_w, ln_b, out);
}